// round 12
// baseline (speedup 1.0000x reference)
#include <cuda_runtime.h>
#include <cuda_bf16.h>
#include <stdint.h>
#include <math.h>

#define B_ 512
#define T_ 64
#define A_ 32
#define H_ 512
#define E_ 32

typedef unsigned long long u64;

// scratch (device globals; allocation forbidden)
__device__ float g_M1[E_ * 64 * H_];          // split-K partials of W1@W2_top
__device__ float g_M1r[E_ * 32 * H_];         // reduced M1 (E,32,512)
__device__ float g_V2[2][B_ * H_];            // split-K partials of bias
__device__ float g_V[B_ * H_];                // reduced bias (B,512)
__device__ __nv_bfloat16 g_yhi[B_ * T_ * H_]; // layer-1 output hi split [b*64+t][k]
__device__ __nv_bfloat16 g_ylo[B_ * T_ * H_]; // layer-1 output lo split
__device__ __nv_bfloat16 g_w3hi[(size_t)E_ * H_ * H_]; // W3^T hi  [e][n][k]
__device__ __nv_bfloat16 g_w3lo[(size_t)E_ * H_ * H_]; // W3^T lo
__device__ int2 g_pairs[272];
__device__ int  g_npairs;

#define DEV __device__ __forceinline__

DEV u64 pack2(float x) { u64 r; asm("mov.b64 %0, {%1, %1};" : "=l"(r) : "f"(x)); return r; }
DEV void fma2(u64 &d, u64 a, u64 b) { asm("fma.rn.f32x2 %0, %1, %2, %0;" : "+l"(d) : "l"(a), "l"(b)); }
DEV float2 unpk(u64 a) { float2 f; asm("mov.b64 {%0, %1}, %2;" : "=f"(f.x), "=f"(f.y) : "l"(a)); return f; }

DEV void cp16(void* dst, const void* src) {
    unsigned d = (unsigned)__cvta_generic_to_shared(dst);
    asm volatile("cp.async.cg.shared.global [%0], [%1], 16;" :: "r"(d), "l"(src));
}
DEV void cp_commit() { asm volatile("cp.async.commit_group;"); }
DEV void cp_wait0()  { asm volatile("cp.async.wait_group 0;"); }

union F4 { float4 v; float f[4]; u64 u[2]; };

DEV float swishf(float z) { return z / (1.0f + expf(-z)); }

DEV uint32_t smem_u32(const void* p) {
    uint32_t a;
    asm("{ .reg .u64 t; cvta.to.shared.u64 t, %1; cvt.u32.u64 %0, t; }" : "=r"(a) : "l"(p));
    return a;
}

DEV void ldsm4(uint32_t* r, uint32_t a) {
    asm volatile("ldmatrix.sync.aligned.m8n8.x4.shared.b16 {%0,%1,%2,%3}, [%4];"
                 : "=r"(r[0]), "=r"(r[1]), "=r"(r[2]), "=r"(r[3]) : "r"(a));
}
DEV void mma16816(float* c, const uint32_t* a, uint32_t b0, uint32_t b1) {
    asm volatile("mma.sync.aligned.m16n8k16.row.col.f32.bf16.bf16.f32 "
                 "{%0,%1,%2,%3}, {%4,%5,%6,%7}, {%8,%9}, {%0,%1,%2,%3};"
                 : "+f"(c[0]), "+f"(c[1]), "+f"(c[2]), "+f"(c[3])
                 : "r"(a[0]), "r"(a[1]), "r"(a[2]), "r"(a[3]), "r"(b0), "r"(b1));
}

// ---------------------------------------------------------------------------
// k_prep: 256 CTAs x 256 threads — M1 + V split-K partials ONLY
// (exact R5 structure, measured 54 us; W3 split moved back to its own kernel)
// ---------------------------------------------------------------------------
__global__ void __launch_bounds__(256) k_prep(const float* __restrict__ ts,
                                              const int*   __restrict__ cat,
                                              const float* __restrict__ W1,
                                              const float* __restrict__ b1,
                                              const float* __restrict__ W2,
                                              const float* __restrict__ b2)
{
    extern __shared__ float sm[];
    const int cid = blockIdx.x;
    const int tid = threadIdx.x;

    if (cid < 128) {
        // ---------------- M1 partial ----------------
        const int e  = cid >> 2;
        const int j0 = ((cid >> 1) & 1) * 256;
        const int kz = cid & 1;
        const int j  = j0 + tid;

        float* w1t = sm;                 // [256 hh][34]
        float* wt  = sm + 256 * 34;      // 2 x [32][256]

        const float* W1e = W1 + e * (A_ * H_);
        const float* W2h = W2 + e * (2 * H_ * H_) + kz * 256 * H_ + j0;

        #pragma unroll
        for (int l = 0; l < 8; l++) {
            int i = tid + l * 256;
            int r = i >> 6, c4 = (i & 63) << 2;
            cp16(wt + r * 256 + c4, W2h + r * H_ + c4);
        }
        cp_commit();

        for (int i = tid; i < 32 * 256; i += 256) {
            int a = i >> 8, hh = i & 255;
            w1t[hh * 34 + a] = W1e[a * H_ + kz * 256 + hh];
        }

        u64 acc[16];
        #pragma unroll
        for (int p = 0; p < 16; p++) acc[p] = 0ULL;

        for (int kt = 0; kt < 8; kt++) {
            cp_wait0();
            __syncthreads();
            if (kt < 7) {
                const float* src = W2h + (kt + 1) * 32 * H_;
                float* dst = wt + ((kt + 1) & 1) * (32 * 256);
                #pragma unroll
                for (int l = 0; l < 8; l++) {
                    int i = tid + l * 256;
                    int r = i >> 6, c4 = (i & 63) << 2;
                    cp16(dst + r * 256 + c4, src + r * H_ + c4);
                }
                cp_commit();
            }
            const float* cur = wt + (kt & 1) * (32 * 256);
            #pragma unroll 2
            for (int hl = 0; hl < 32; hl++) {
                const int hh = kt * 32 + hl;
                u64 wd = pack2(cur[hl * 256 + tid]);
                #pragma unroll
                for (int p = 0; p < 16; p++)
                    fma2(acc[p], *(const u64*)&w1t[hh * 34 + 2 * p], wd);
            }
        }
        float* M1e = g_M1 + e * (64 * H_) + kz * 32 * H_;
        #pragma unroll
        for (int p = 0; p < 16; p++) {
            float2 f = unpk(acc[p]);
            M1e[(2 * p) * H_ + j]     = f.x;
            M1e[(2 * p + 1) * H_ + j] = f.y;
        }
    } else {
        // ---------------- V partial ----------------
        const int vc = cid - 128;
        const int e  = vc >> 2;
        const int j0 = ((vc >> 1) & 1) * 256;
        const int kz = vc & 1;
        const int j  = j0 + tid;

        float* trig = sm;                         // [256 k][16 b]
        float* wt   = sm + 256 * 16;              // 2 x [32][256]
        int*   list = (int*)(sm + 256 * 16 + 2 * 32 * 256);
        int*   pn   = list + B_;

        if (tid == 0) *pn = 0;
        __syncthreads();
        for (int b = tid; b < B_; b += 256)
            if (cat[b] == e) { int p = atomicAdd(pn, 1); list[p] = b; }

        int nzl = (b1[e * H_ + kz * 256 + tid] != 0.0f);
        const int nz = __syncthreads_or(nzl);
        const int nb = *pn;

        const float* W2e = W2 + e * (2 * H_ * H_);
        float cb = (kz == 0) ? b2[e * H_ + j] : 0.0f;
        if (nz) {
            #pragma unroll 8
            for (int h = 0; h < 256; h++)
                cb += b1[e * H_ + kz * 256 + h] * W2e[(kz * 256 + h) * H_ + j];
        }

        const float L = 9.210340371976184f / 256.0f;
        const float* W2bot = W2e + H_ * H_ + kz * 256 * H_ + j0;

        for (int bg = 0; bg * 16 < nb; bg++) {
            const int m = min(16, nb - bg * 16);
            __syncthreads();
            for (int i = tid; i < 16 * 256; i += 256) {
                int k = i >> 4, q = i & 15;
                float t = (q < m) ? ts[list[bg * 16 + q]] : 0.0f;
                float ang = t * expf(-L * (float)k);
                trig[k * 16 + q] = kz ? cosf(ang) : sinf(ang);
            }
            #pragma unroll
            for (int l = 0; l < 8; l++) {
                int i = tid + l * 256;
                int r = i >> 6, c4 = (i & 63) << 2;
                cp16(wt + r * 256 + c4, W2bot + r * H_ + c4);
            }
            cp_commit();

            u64 acc[8];
            #pragma unroll
            for (int q = 0; q < 8; q++) acc[q] = 0ULL;

            for (int kt = 0; kt < 8; kt++) {
                cp_wait0();
                __syncthreads();
                if (kt < 7) {
                    const float* src = W2bot + (kt + 1) * 32 * H_;
                    float* dst = wt + ((kt + 1) & 1) * (32 * 256);
                    #pragma unroll
                    for (int l = 0; l < 8; l++) {
                        int i = tid + l * 256;
                        int r = i >> 6, c4 = (i & 63) << 2;
                        cp16(dst + r * 256 + c4, src + r * H_ + c4);
                    }
                    cp_commit();
                }
                const float* cur = wt + (kt & 1) * (32 * 256);
                #pragma unroll 2
                for (int kk = 0; kk < 32; kk++) {
                    const int k = kt * 32 + kk;
                    u64 wd = pack2(cur[kk * 256 + tid]);
                    #pragma unroll
                    for (int q = 0; q < 8; q++)
                        fma2(acc[q], *(const u64*)&trig[k * 16 + 2 * q], wd);
                }
            }
            #pragma unroll
            for (int q = 0; q < 8; q++) {
                float2 f = unpk(acc[q]);
                if (2 * q < m)     g_V2[kz][list[bg * 16 + 2 * q] * H_ + j]     = f.x + cb;
                if (2 * q + 1 < m) g_V2[kz][list[bg * 16 + 2 * q + 1] * H_ + j] = f.y + cb;
            }
        }
    }
}

// ---------------------------------------------------------------------------
// k_w3: standalone W3 transpose + bf16 split (exact R7 structure, ~12 us).
// grid (E, 8, 8) x 256 threads; 17 KB static smem -> high occupancy.
// ---------------------------------------------------------------------------
__global__ void __launch_bounds__(256) k_w3(const float* __restrict__ W3)
{
    __shared__ float tile[64][65];
    const int e  = blockIdx.x;
    const int kb = blockIdx.y * 64;
    const int nb = blockIdx.z * 64;
    const float* src = W3 + ((size_t)e * H_ + kb) * H_ + nb;

    #pragma unroll
    for (int l = 0; l < 16; l++) {
        int i = threadIdx.x + l * 256;
        int r = i >> 6, c = i & 63;
        tile[r][c] = src[(size_t)r * H_ + c];
    }
    __syncthreads();
    #pragma unroll
    for (int l = 0; l < 16; l++) {
        int i = threadIdx.x + l * 256;
        int r = i >> 6, c = i & 63;          // r = n-local, c = k-local
        float x = tile[c][r];
        __nv_bfloat16 hi = __float2bfloat16(x);
        __nv_bfloat16 lo = __float2bfloat16(x - __bfloat162float(hi));
        size_t o = ((size_t)e * H_ + nb + r) * H_ + kb + c;
        g_w3hi[o] = hi;
        g_w3lo[o] = lo;
    }
}

// ---------------------------------------------------------------------------
// k_red: fold split-K partials + build pair list (CTA 384).
// ---------------------------------------------------------------------------
__global__ void __launch_bounds__(512) k_red(const int* __restrict__ cat)
{
    if (blockIdx.x == 384) {
        // pair list: 1 warp, thread e scans cat
        const int tid = threadIdx.x;
        if (tid < 32) {
            const int e = tid;
            if (e == 0) g_npairs = 0;
            __syncwarp();
            int prev = -1;
            for (int b = 0; b < B_; b++) {
                if (cat[b] == e) {
                    if (prev < 0) prev = b;
                    else {
                        int p = atomicAdd(&g_npairs, 1);
                        g_pairs[p] = make_int2(prev, b);
                        prev = -1;
                    }
                }
            }
            if (prev >= 0) {
                int p = atomicAdd(&g_npairs, 1);
                g_pairs[p] = make_int2(prev, -1);
            }
        }
        return;
    }
    const int i = blockIdx.x * 512 + threadIdx.x;
    const float4* m1 = (const float4*)g_M1;
    if (i < 131072) {
        int e = i >> 12, r = i & 4095;
        F4 a, b;
        a.v = m1[e * 8192 + r];
        b.v = m1[e * 8192 + 4096 + r];
        #pragma unroll
        for (int q = 0; q < 4; q++) a.f[q] += b.f[q];
        ((float4*)g_M1r)[i] = a.v;
    } else {
        int r = i - 131072;
        F4 a, b;
        a.v = ((const float4*)g_V2[0])[r];
        b.v = ((const float4*)g_V2[1])[r];
        #pragma unroll
        for (int q = 0; q < 4; q++) a.f[q] += b.f[q];
        ((float4*)g_V)[r] = a.v;
    }
}

// ---------------------------------------------------------------------------
// k_y helpers (SIMT layer-1)
// ---------------------------------------------------------------------------
template <int NK4>
DEV void mma4(const float* __restrict__ wb, const float* __restrict__ yrow,
              int ystride, u64 (&acc)[4][4], int t0, int jb)
{
    #pragma unroll
    for (int k4 = 0; k4 < NK4; k4++) {
        F4 yv[4];
        #pragma unroll
        for (int r = 0; r < 4; r++)
            yv[r].v = *(const float4*)&yrow[(t0 + r) * ystride + k4 * 4];
        #pragma unroll
        for (int kk = 0; kk < 4; kk++) {
            F4 w0, w1;
            w0.v = *(const float4*)&wb[(k4 * 4 + kk) * 256 + jb];
            w1.v = *(const float4*)&wb[(k4 * 4 + kk) * 256 + jb + 128];
            #pragma unroll
            for (int r = 0; r < 4; r++) {
                u64 yd = pack2(yv[r].f[kk]);
                fma2(acc[r][0], yd, w0.u[0]);
                fma2(acc[r][1], yd, w0.u[1]);
                fma2(acc[r][2], yd, w1.u[0]);
                fma2(acc[r][3], yd, w1.u[1]);
            }
        }
    }
}

// ---------------------------------------------------------------------------
// k_y: y = swish(actions @ M1r + v), split to bf16 hi/lo.  grid (B,2) x 512
// (R8 version, measured fast)
// ---------------------------------------------------------------------------
__global__ void __launch_bounds__(512) k_y(const float* __restrict__ actions,
                                           const int*   __restrict__ cat_ids)
{
    extern __shared__ float sm[];
    float* m1  = sm;              // [32][256]
    float* act = sm + 32 * 256;   // [64][32]

    const int tid = threadIdx.x;
    const int b   = blockIdx.x;
    const int jh  = blockIdx.y;
    const int e   = cat_ids[b];
    const int t0  = (tid >> 5) * 4;
    const int jb  = (tid & 31) * 4;

    const float* M1e  = g_M1r + e * (32 * H_) + jh * 256;
    const float* actb = actions + b * (T_ * A_);

    #pragma unroll
    for (int l = 0; l < 4; l++) {
        int i = tid + l * 512;
        int r = i >> 6, c4 = (i & 63) << 2;
        cp16(m1 + r * 256 + c4, M1e + (size_t)r * H_ + c4);
    }
    cp16(act + tid * 4, actb + tid * 4);
    cp_commit();
    cp_wait0();
    __syncthreads();

    u64 acc[4][4];
    #pragma unroll
    for (int r = 0; r < 4; r++)
        #pragma unroll
        for (int c = 0; c < 4; c++) acc[r][c] = 0ULL;

    mma4<4>(m1,            act,      32, acc, t0, jb);
    mma4<4>(m1 + 16 * 256, act + 16, 32, acc, t0, jb);

    const float* vp = g_V + b * H_ + jh * 256;
    F4 v0, v1;
    v0.v = *(const float4*)&vp[jb];
    v1.v = *(const float4*)&vp[jb + 128];

    #pragma unroll
    for (int r = 0; r < 4; r++) {
        float y[8];
        float2 a0 = unpk(acc[r][0]), a1 = unpk(acc[r][1]);
        float2 a2 = unpk(acc[r][2]), a3 = unpk(acc[r][3]);
        y[0] = swishf(a0.x + v0.f[0]); y[1] = swishf(a0.y + v0.f[1]);
        y[2] = swishf(a1.x + v0.f[2]); y[3] = swishf(a1.y + v0.f[3]);
        y[4] = swishf(a2.x + v1.f[0]); y[5] = swishf(a2.y + v1.f[1]);
        y[6] = swishf(a3.x + v1.f[2]); y[7] = swishf(a3.y + v1.f[3]);

        __nv_bfloat16 hi[8], lo[8];
        #pragma unroll
        for (int q = 0; q < 8; q++) {
            hi[q] = __float2bfloat16(y[q]);
            lo[q] = __float2bfloat16(y[q] - __bfloat162float(hi[q]));
        }
        size_t base = ((size_t)b * 64 + t0 + r) * 512 + jh * 256;
        *(uint2*)&g_yhi[base + jb]       = *(uint2*)&hi[0];
        *(uint2*)&g_yhi[base + jb + 128] = *(uint2*)&hi[4];
        *(uint2*)&g_ylo[base + jb]       = *(uint2*)&lo[0];
        *(uint2*)&g_ylo[base + jb + 128] = *(uint2*)&lo[4];
    }
}

// ---------------------------------------------------------------------------
// k_mma: layer 2 on warp-level HMMA, bf16x3 split, fp32 accum.
//  (EXACT R8 version — measured 156.7 us.)
//  grid (272, 4) x 256 threads.  CTA (pid, jq): M=128 pair rows, N=128 quarter.
//  Warp grid 4m x 2n -> warp tile 32x64, 16 frag accumulators; inner loop is
//  3 passes (hh, hl, lh) sweeping all 16 accs (no HMMA accumulator RAW).
// ---------------------------------------------------------------------------
#define KPB  144
#define AHI_OFF  0
#define ALO_OFF  18432
#define BHI_OFF  36864
#define BLO_OFF  55296
#define STAGE_SZ 73728

__global__ void __launch_bounds__(256, 1) k_mma(const int*   __restrict__ cat_ids,
                                                const float* __restrict__ b3,
                                                float*       __restrict__ out)
{
    extern __shared__ __align__(16) char smem[];

    const int pid = blockIdx.x;
    const int jq  = blockIdx.y;
    if (pid >= g_npairs) return;

    const int2 pr = g_pairs[pid];
    const int b0  = pr.x;
    const int b1  = (pr.y < 0) ? pr.x : pr.y;
    const bool has_b1 = (pr.y >= 0);
    const int e   = cat_ids[b0];

    const int tid  = threadIdx.x;
    const int wid  = tid >> 5;
    const int lane = tid & 31;
    const int wm   = wid & 3;    // 4 m-strips of 32
    const int wn   = wid >> 2;   // 2 n-strips of 64

    const __nv_bfloat16* yh = g_yhi;
    const __nv_bfloat16* yl = g_ylo;
    const __nv_bfloat16* wh = g_w3hi + ((size_t)e * H_ + jq * 128) * H_;
    const __nv_bfloat16* wl = g_w3lo + ((size_t)e * H_ + jq * 128) * H_;

    const uint32_t sb = smem_u32(smem);

    // per-lane ldmatrix offsets
    const uint32_t arow  = (lane & 7) | (((lane >> 3) & 1) << 3);
    const uint32_t aoff  = (wm * 32 + arow) * KPB + (lane >> 4) * 16;
    const uint32_t nrow  = (lane & 7) | (((lane >> 4) & 1) << 3);
    const uint32_t boff  = (wn * 64 + nrow) * KPB + ((lane >> 3) & 1) * 16;

    #define LOADCHUNK(kc, p) do {                                               \
        char* _d = smem + (p) * STAGE_SZ;                                       \
        _Pragma("unroll")                                                       \
        for (int _l = 0; _l < 4; _l++) {                                        \
            int _i = tid + _l * 256;                                            \
            int _row = _i >> 3, _k8 = _i & 7;                                   \
            uint32_t _off = _row * KPB + _k8 * 16;                              \
            size_t _g = ((size_t)(((_row < 64) ? b0 : b1) * 64 + (_row & 63))) * 512 \
                        + (kc) * 64 + _k8 * 8;                                  \
            cp16(_d + AHI_OFF + _off, yh + _g);                                 \
            cp16(_d + ALO_OFF + _off, yl + _g);                                 \
        }                                                                       \
        _Pragma("unroll")                                                       \
        for (int _l = 0; _l < 4; _l++) {                                        \
            int _i = tid + _l * 256;                                            \
            int _n = _i >> 3, _k8 = _i & 7;                                     \
            uint32_t _off = _n * KPB + _k8 * 16;                                \
            size_t _g = (size_t)_n * 512 + (kc) * 64 + _k8 * 8;                 \
            cp16(_d + BHI_OFF + _off, wh + _g);                                 \
            cp16(_d + BLO_OFF + _off, wl + _g);                                 \
        }                                                                       \
        cp_commit();                                                            \
    } while (0)

    float acc[2][8][4];
    #pragma unroll
    for (int mt = 0; mt < 2; mt++)
        #pragma unroll
        for (int nt = 0; nt < 8; nt++)
            #pragma unroll
            for (int q = 0; q < 4; q++) acc[mt][nt][q] = 0.0f;

    LOADCHUNK(0, 0);

    for (int kc = 0; kc < 8; kc++) {
        cp_wait0();
        __syncthreads();
        if (kc < 7) LOADCHUNK(kc + 1, (kc + 1) & 1);

        const uint32_t stg = sb + (kc & 1) * STAGE_SZ;
        #pragma unroll
        for (int ks = 0; ks < 4; ks++) {
            const uint32_t kb = ks * 32;  // 16 bf16 = 32 bytes per k-step
            uint32_t ah[2][4], al[2][4], bh[4][4], bl[4][4];

            #pragma unroll
            for (int mt = 0; mt < 2; mt++)
                ldsm4(ah[mt], stg + aoff + mt * (16 * KPB) + kb + AHI_OFF);
            #pragma unroll
            for (int nt = 0; nt < 4; nt++)
                ldsm4(bh[nt], stg + boff + nt * (16 * KPB) + kb + BHI_OFF);

            // pass 1: hi * hi  (16 distinct accumulators)
            #pragma unroll
            for (int nt = 0; nt < 4; nt++)
                #pragma unroll
                for (int mt = 0; mt < 2; mt++) {
                    mma16816(acc[mt][2 * nt],     ah[mt], bh[nt][0], bh[nt][1]);
                    mma16816(acc[mt][2 * nt + 1], ah[mt], bh[nt][2], bh[nt][3]);
                }

            #pragma unroll
            for (int nt = 0; nt < 4; nt++)
                ldsm4(bl[nt], stg + boff + nt * (16 * KPB) + kb + BLO_OFF);

            // pass 2: hi * lo
            #pragma unroll
            for (int nt = 0; nt < 4; nt++)
                #pragma unroll
                for (int mt = 0; mt < 2; mt++) {
                    mma16816(acc[mt][2 * nt],     ah[mt], bl[nt][0], bl[nt][1]);
                    mma16816(acc[mt][2 * nt + 1], ah[mt], bl[nt][2], bl[nt][3]);
                }

            #pragma unroll
            for (int mt = 0; mt < 2; mt++)
                ldsm4(al[mt], stg + aoff + mt * (16 * KPB) + kb + ALO_OFF);

            // pass 3: lo * hi
            #pragma unroll
            for (int nt = 0; nt < 4; nt++)
                #pragma unroll
                for (int mt = 0; mt < 2; mt++) {
                    mma16816(acc[mt][2 * nt],     al[mt], bh[nt][0], bh[nt][1]);
                    mma16816(acc[mt][2 * nt + 1], al[mt], bh[nt][2], bh[nt][3]);
                }
        }
    }

    // epilogue: c frag (m16n8): thread t -> rows {t/4, t/4+8}, cols {2(t%4), +1}
    {
        const int rgrp = lane >> 2;
        const int cgrp = 2 * (lane & 3);
        const float* b3e = b3 + e * H_;
        #pragma unroll
        for (int mt = 0; mt < 2; mt++) {
            const int r0 = wm * 32 + mt * 16 + rgrp;       // 0..127
            #pragma unroll
            for (int half = 0; half < 2; half++) {
                const int r = r0 + half * 8;
                const int bsel = (r < 64) ? b0 : b1;
                if (r >= 64 && !has_b1) continue;
                float* outr = out + ((size_t)bsel * 64 + (r & 63)) * 512;
                #pragma unroll
                for (int nt = 0; nt < 8; nt++) {
                    const int col = jq * 128 + wn * 64 + nt * 8 + cgrp;
                    float2 o;
                    o.x = acc[mt][nt][half * 2 + 0] + b3e[col];
                    o.y = acc[mt][nt][half * 2 + 1] + b3e[col + 1];
                    *(float2*)&outr[col] = o;
                }
            }
        }
    }
    #undef LOADCHUNK
}

// ---------------------------------------------------------------------------
extern "C" void kernel_launch(void* const* d_in, const int* in_sizes, int n_in,
                              void* d_out, int out_size)
{
    const float* actions = (const float*)d_in[0];
    const float* ts      = (const float*)d_in[1];
    const int*   cat     = (const int*)  d_in[2];
    const float* W1      = (const float*)d_in[3];
    const float* b1      = (const float*)d_in[4];
    const float* W2      = (const float*)d_in[5];
    const float* b2      = (const float*)d_in[6];
    const float* W3      = (const float*)d_in[7];
    const float* b3      = (const float*)d_in[8];
    float*       out     = (float*)d_out;

    const int smem_prep = (256 * 34 + 2 * 32 * 256) * 4;   // ~100 KB
    const int smem_y    = (32 * 256 + 64 * 32) * 4;        //  40 KB
    const int smem_mma  = 2 * STAGE_SZ;                    // 144 KB

    cudaFuncSetAttribute(k_prep, cudaFuncAttributeMaxDynamicSharedMemorySize, smem_prep);
    cudaFuncSetAttribute(k_y,    cudaFuncAttributeMaxDynamicSharedMemorySize, smem_y);
    cudaFuncSetAttribute(k_mma,  cudaFuncAttributeMaxDynamicSharedMemorySize, smem_mma);

    k_prep<<<256, 256, smem_prep>>>(ts, cat, W1, b1, W2, b2);
    k_w3  <<<dim3(E_, 8, 8), 256>>>(W3);
    k_red <<<385, 512>>>(cat);
    k_y   <<<dim3(B_, 2), 512, smem_y>>>(actions, cat);
    k_mma <<<dim3(272, 4), 256, smem_mma>>>(cat, b3, out);
}

// round 13
// speedup vs baseline: 1.0959x; 1.0959x over previous
#include <cuda_runtime.h>
#include <cuda_bf16.h>
#include <stdint.h>
#include <math.h>

#define B_ 512
#define T_ 64
#define A_ 32
#define H_ 512
#define E_ 32

typedef unsigned long long u64;

// scratch (device globals; allocation forbidden)
__device__ float g_M1[E_ * 64 * H_];          // split-K partials of W1@W2_top
__device__ float g_M1r[E_ * 32 * H_];         // reduced M1 (E,32,512)
__device__ float g_V2[2][B_ * H_];            // split-K partials of bias
__device__ float g_V[B_ * H_];                // reduced bias (B,512)
__device__ __nv_bfloat16 g_yhi[B_ * T_ * H_]; // layer-1 output hi split [b*64+t][k]
__device__ __nv_bfloat16 g_ylo[B_ * T_ * H_]; // layer-1 output lo split
__device__ __nv_bfloat16 g_w3hi[(size_t)E_ * H_ * H_]; // W3^T hi  [e][n][k]
__device__ __nv_bfloat16 g_w3lo[(size_t)E_ * H_ * H_]; // W3^T lo
__device__ int2 g_pairs[272];
__device__ int  g_npairs;

#define DEV __device__ __forceinline__

DEV u64 pack2(float x) { u64 r; asm("mov.b64 %0, {%1, %1};" : "=l"(r) : "f"(x)); return r; }
DEV void fma2(u64 &d, u64 a, u64 b) { asm("fma.rn.f32x2 %0, %1, %2, %0;" : "+l"(d) : "l"(a), "l"(b)); }
DEV float2 unpk(u64 a) { float2 f; asm("mov.b64 {%0, %1}, %2;" : "=f"(f.x), "=f"(f.y) : "l"(a)); return f; }

DEV void cp16(void* dst, const void* src) {
    unsigned d = (unsigned)__cvta_generic_to_shared(dst);
    asm volatile("cp.async.cg.shared.global [%0], [%1], 16;" :: "r"(d), "l"(src));
}
DEV void cp_commit() { asm volatile("cp.async.commit_group;"); }
DEV void cp_wait0()  { asm volatile("cp.async.wait_group 0;"); }

union F4 { float4 v; float f[4]; u64 u[2]; };

DEV float swishf(float z) { return z / (1.0f + expf(-z)); }

DEV uint32_t smem_u32(const void* p) {
    uint32_t a;
    asm("{ .reg .u64 t; cvta.to.shared.u64 t, %1; cvt.u32.u64 %0, t; }" : "=r"(a) : "l"(p));
    return a;
}

DEV void ldsm4(uint32_t* r, uint32_t a) {
    asm volatile("ldmatrix.sync.aligned.m8n8.x4.shared.b16 {%0,%1,%2,%3}, [%4];"
                 : "=r"(r[0]), "=r"(r[1]), "=r"(r[2]), "=r"(r[3]) : "r"(a));
}
DEV void mma16816(float* c, const uint32_t* a, uint32_t b0, uint32_t b1) {
    asm volatile("mma.sync.aligned.m16n8k16.row.col.f32.bf16.bf16.f32 "
                 "{%0,%1,%2,%3}, {%4,%5,%6,%7}, {%8,%9}, {%0,%1,%2,%3};"
                 : "+f"(c[0]), "+f"(c[1]), "+f"(c[2]), "+f"(c[3])
                 : "r"(a[0]), "r"(a[1]), "r"(a[2]), "r"(a[3]), "r"(b0), "r"(b1));
}

// ---------------------------------------------------------------------------
// k_prep: 769 CTAs x 256 threads (EXACT R8 version — measured best total)
//   [0,128)    M1 split-K partial      (e = cid>>2, j-half, k-half)
//   [128,256)  V split-K partial
//   [256,768)  W3 -> transposed bf16 hi/lo splits (4 64x64 tiles per CTA)
//   768        pair list (1 warp)
// ---------------------------------------------------------------------------
__global__ void __launch_bounds__(256) k_prep(const float* __restrict__ ts,
                                              const int*   __restrict__ cat,
                                              const float* __restrict__ W1,
                                              const float* __restrict__ b1,
                                              const float* __restrict__ W2,
                                              const float* __restrict__ b2,
                                              const float* __restrict__ W3)
{
    extern __shared__ float sm[];
    const int cid = blockIdx.x;
    const int tid = threadIdx.x;

    if (cid < 128) {
        // ---------------- M1 partial ----------------
        const int e  = cid >> 2;
        const int j0 = ((cid >> 1) & 1) * 256;
        const int kz = cid & 1;
        const int j  = j0 + tid;

        float* w1t = sm;                 // [256 hh][34]
        float* wt  = sm + 256 * 34;      // 2 x [32][256]

        const float* W1e = W1 + e * (A_ * H_);
        const float* W2h = W2 + e * (2 * H_ * H_) + kz * 256 * H_ + j0;

        #pragma unroll
        for (int l = 0; l < 8; l++) {
            int i = tid + l * 256;
            int r = i >> 6, c4 = (i & 63) << 2;
            cp16(wt + r * 256 + c4, W2h + r * H_ + c4);
        }
        cp_commit();

        for (int i = tid; i < 32 * 256; i += 256) {
            int a = i >> 8, hh = i & 255;
            w1t[hh * 34 + a] = W1e[a * H_ + kz * 256 + hh];
        }

        u64 acc[16];
        #pragma unroll
        for (int p = 0; p < 16; p++) acc[p] = 0ULL;

        for (int kt = 0; kt < 8; kt++) {
            cp_wait0();
            __syncthreads();
            if (kt < 7) {
                const float* src = W2h + (kt + 1) * 32 * H_;
                float* dst = wt + ((kt + 1) & 1) * (32 * 256);
                #pragma unroll
                for (int l = 0; l < 8; l++) {
                    int i = tid + l * 256;
                    int r = i >> 6, c4 = (i & 63) << 2;
                    cp16(dst + r * 256 + c4, src + r * H_ + c4);
                }
                cp_commit();
            }
            const float* cur = wt + (kt & 1) * (32 * 256);
            #pragma unroll 2
            for (int hl = 0; hl < 32; hl++) {
                const int hh = kt * 32 + hl;
                u64 wd = pack2(cur[hl * 256 + tid]);
                #pragma unroll
                for (int p = 0; p < 16; p++)
                    fma2(acc[p], *(const u64*)&w1t[hh * 34 + 2 * p], wd);
            }
        }
        float* M1e = g_M1 + e * (64 * H_) + kz * 32 * H_;
        #pragma unroll
        for (int p = 0; p < 16; p++) {
            float2 f = unpk(acc[p]);
            M1e[(2 * p) * H_ + j]     = f.x;
            M1e[(2 * p + 1) * H_ + j] = f.y;
        }
    } else if (cid < 256) {
        // ---------------- V partial ----------------
        const int vc = cid - 128;
        const int e  = vc >> 2;
        const int j0 = ((vc >> 1) & 1) * 256;
        const int kz = vc & 1;
        const int j  = j0 + tid;

        float* trig = sm;                         // [256 k][16 b]
        float* wt   = sm + 256 * 16;              // 2 x [32][256]
        int*   list = (int*)(sm + 256 * 16 + 2 * 32 * 256);
        int*   pn   = list + B_;

        if (tid == 0) *pn = 0;
        __syncthreads();
        for (int b = tid; b < B_; b += 256)
            if (cat[b] == e) { int p = atomicAdd(pn, 1); list[p] = b; }

        int nzl = (b1[e * H_ + kz * 256 + tid] != 0.0f);
        const int nz = __syncthreads_or(nzl);
        const int nb = *pn;

        const float* W2e = W2 + e * (2 * H_ * H_);
        float cb = (kz == 0) ? b2[e * H_ + j] : 0.0f;
        if (nz) {
            #pragma unroll 8
            for (int h = 0; h < 256; h++)
                cb += b1[e * H_ + kz * 256 + h] * W2e[(kz * 256 + h) * H_ + j];
        }

        const float L = 9.210340371976184f / 256.0f;
        const float* W2bot = W2e + H_ * H_ + kz * 256 * H_ + j0;

        for (int bg = 0; bg * 16 < nb; bg++) {
            const int m = min(16, nb - bg * 16);
            __syncthreads();
            for (int i = tid; i < 16 * 256; i += 256) {
                int k = i >> 4, q = i & 15;
                float t = (q < m) ? ts[list[bg * 16 + q]] : 0.0f;
                float ang = t * expf(-L * (float)k);
                trig[k * 16 + q] = kz ? cosf(ang) : sinf(ang);
            }
            #pragma unroll
            for (int l = 0; l < 8; l++) {
                int i = tid + l * 256;
                int r = i >> 6, c4 = (i & 63) << 2;
                cp16(wt + r * 256 + c4, W2bot + r * H_ + c4);
            }
            cp_commit();

            u64 acc[8];
            #pragma unroll
            for (int q = 0; q < 8; q++) acc[q] = 0ULL;

            for (int kt = 0; kt < 8; kt++) {
                cp_wait0();
                __syncthreads();
                if (kt < 7) {
                    const float* src = W2bot + (kt + 1) * 32 * H_;
                    float* dst = wt + ((kt + 1) & 1) * (32 * 256);
                    #pragma unroll
                    for (int l = 0; l < 8; l++) {
                        int i = tid + l * 256;
                        int r = i >> 6, c4 = (i & 63) << 2;
                        cp16(dst + r * 256 + c4, src + r * H_ + c4);
                    }
                    cp_commit();
                }
                const float* cur = wt + (kt & 1) * (32 * 256);
                #pragma unroll 2
                for (int kk = 0; kk < 32; kk++) {
                    const int k = kt * 32 + kk;
                    u64 wd = pack2(cur[kk * 256 + tid]);
                    #pragma unroll
                    for (int q = 0; q < 8; q++)
                        fma2(acc[q], *(const u64*)&trig[k * 16 + 2 * q], wd);
                }
            }
            #pragma unroll
            for (int q = 0; q < 8; q++) {
                float2 f = unpk(acc[q]);
                if (2 * q < m)     g_V2[kz][list[bg * 16 + 2 * q] * H_ + j]     = f.x + cb;
                if (2 * q + 1 < m) g_V2[kz][list[bg * 16 + 2 * q + 1] * H_ + j] = f.y + cb;
            }
        }
    } else if (cid < 768) {
        // ---------------- W3 transpose + bf16 split (4 tiles) ----------------
        float (*tile)[65] = (float(*)[65])sm;     // [64][65]
        const int wc = cid - 256;                 // 0..511
        const int e  = wc >> 4;
        const int tbase = (wc & 15) * 4;
        #pragma unroll
        for (int ti = 0; ti < 4; ti++) {
            const int t  = tbase + ti;            // 0..63
            const int kb = (t >> 3) * 64;
            const int nb = (t & 7) * 64;
            const float* src = W3 + ((size_t)e * H_ + kb) * H_ + nb;
            __syncthreads();
            #pragma unroll
            for (int l = 0; l < 16; l++) {
                int i = tid + l * 256;
                int r = i >> 6, c = i & 63;
                tile[r][c] = src[(size_t)r * H_ + c];
            }
            __syncthreads();
            #pragma unroll
            for (int l = 0; l < 16; l++) {
                int i = tid + l * 256;
                int r = i >> 6, c = i & 63;        // r = n-local, c = k-local
                float x = tile[c][r];
                __nv_bfloat16 hi = __float2bfloat16(x);
                __nv_bfloat16 lo = __float2bfloat16(x - __bfloat162float(hi));
                size_t o = ((size_t)e * H_ + nb + r) * H_ + kb + c;
                g_w3hi[o] = hi;
                g_w3lo[o] = lo;
            }
        }
    } else {
        // ---------------- pair list (1 warp) ----------------
        if (tid < 32) {
            const int e = tid;
            if (e == 0) g_npairs = 0;
            __syncwarp();
            int prev = -1;
            for (int b = 0; b < B_; b++) {
                if (cat[b] == e) {
                    if (prev < 0) prev = b;
                    else {
                        int p = atomicAdd(&g_npairs, 1);
                        g_pairs[p] = make_int2(prev, b);
                        prev = -1;
                    }
                }
            }
            if (prev >= 0) {
                int p = atomicAdd(&g_npairs, 1);
                g_pairs[p] = make_int2(prev, -1);
            }
        }
    }
}

// ---------------------------------------------------------------------------
// k_red: fold split-K partials (R8 version, measured 5.4 us)
// ---------------------------------------------------------------------------
__global__ void __launch_bounds__(512) k_red()
{
    const int i = blockIdx.x * 512 + threadIdx.x;
    const float4* m1 = (const float4*)g_M1;
    if (i < 131072) {
        int e = i >> 12, r = i & 4095;
        F4 a, b;
        a.v = m1[e * 8192 + r];
        b.v = m1[e * 8192 + 4096 + r];
        #pragma unroll
        for (int q = 0; q < 4; q++) a.f[q] += b.f[q];
        ((float4*)g_M1r)[i] = a.v;
    } else {
        int r = i - 131072;
        F4 a, b;
        a.v = ((const float4*)g_V2[0])[r];
        b.v = ((const float4*)g_V2[1])[r];
        #pragma unroll
        for (int q = 0; q < 4; q++) a.f[q] += b.f[q];
        ((float4*)g_V)[r] = a.v;
    }
}

// ---------------------------------------------------------------------------
// k_y helpers (SIMT layer-1)
// ---------------------------------------------------------------------------
template <int NK4>
DEV void mma4(const float* __restrict__ wb, const float* __restrict__ yrow,
              int ystride, u64 (&acc)[4][4], int t0, int jb)
{
    #pragma unroll
    for (int k4 = 0; k4 < NK4; k4++) {
        F4 yv[4];
        #pragma unroll
        for (int r = 0; r < 4; r++)
            yv[r].v = *(const float4*)&yrow[(t0 + r) * ystride + k4 * 4];
        #pragma unroll
        for (int kk = 0; kk < 4; kk++) {
            F4 w0, w1;
            w0.v = *(const float4*)&wb[(k4 * 4 + kk) * 256 + jb];
            w1.v = *(const float4*)&wb[(k4 * 4 + kk) * 256 + jb + 128];
            #pragma unroll
            for (int r = 0; r < 4; r++) {
                u64 yd = pack2(yv[r].f[kk]);
                fma2(acc[r][0], yd, w0.u[0]);
                fma2(acc[r][1], yd, w0.u[1]);
                fma2(acc[r][2], yd, w1.u[0]);
                fma2(acc[r][3], yd, w1.u[1]);
            }
        }
    }
}

// ---------------------------------------------------------------------------
// k_y: y = swish(actions @ M1r + v), split to bf16 hi/lo.  grid (B,2) x 512
// (R8 version)
// ---------------------------------------------------------------------------
__global__ void __launch_bounds__(512) k_y(const float* __restrict__ actions,
                                           const int*   __restrict__ cat_ids)
{
    extern __shared__ float sm[];
    float* m1  = sm;              // [32][256]
    float* act = sm + 32 * 256;   // [64][32]

    const int tid = threadIdx.x;
    const int b   = blockIdx.x;
    const int jh  = blockIdx.y;
    const int e   = cat_ids[b];
    const int t0  = (tid >> 5) * 4;
    const int jb  = (tid & 31) * 4;

    const float* M1e  = g_M1r + e * (32 * H_) + jh * 256;
    const float* actb = actions + b * (T_ * A_);

    #pragma unroll
    for (int l = 0; l < 4; l++) {
        int i = tid + l * 512;
        int r = i >> 6, c4 = (i & 63) << 2;
        cp16(m1 + r * 256 + c4, M1e + (size_t)r * H_ + c4);
    }
    cp16(act + tid * 4, actb + tid * 4);
    cp_commit();
    cp_wait0();
    __syncthreads();

    u64 acc[4][4];
    #pragma unroll
    for (int r = 0; r < 4; r++)
        #pragma unroll
        for (int c = 0; c < 4; c++) acc[r][c] = 0ULL;

    mma4<4>(m1,            act,      32, acc, t0, jb);
    mma4<4>(m1 + 16 * 256, act + 16, 32, acc, t0, jb);

    const float* vp = g_V + b * H_ + jh * 256;
    F4 v0, v1;
    v0.v = *(const float4*)&vp[jb];
    v1.v = *(const float4*)&vp[jb + 128];

    #pragma unroll
    for (int r = 0; r < 4; r++) {
        float y[8];
        float2 a0 = unpk(acc[r][0]), a1 = unpk(acc[r][1]);
        float2 a2 = unpk(acc[r][2]), a3 = unpk(acc[r][3]);
        y[0] = swishf(a0.x + v0.f[0]); y[1] = swishf(a0.y + v0.f[1]);
        y[2] = swishf(a1.x + v0.f[2]); y[3] = swishf(a1.y + v0.f[3]);
        y[4] = swishf(a2.x + v1.f[0]); y[5] = swishf(a2.y + v1.f[1]);
        y[6] = swishf(a3.x + v1.f[2]); y[7] = swishf(a3.y + v1.f[3]);

        __nv_bfloat16 hi[8], lo[8];
        #pragma unroll
        for (int q = 0; q < 8; q++) {
            hi[q] = __float2bfloat16(y[q]);
            lo[q] = __float2bfloat16(y[q] - __bfloat162float(hi[q]));
        }
        size_t base = ((size_t)b * 64 + t0 + r) * 512 + jh * 256;
        *(uint2*)&g_yhi[base + jb]       = *(uint2*)&hi[0];
        *(uint2*)&g_yhi[base + jb + 128] = *(uint2*)&hi[4];
        *(uint2*)&g_ylo[base + jb]       = *(uint2*)&lo[0];
        *(uint2*)&g_ylo[base + jb + 128] = *(uint2*)&lo[4];
    }
}

// ---------------------------------------------------------------------------
// k_mma: layer 2 on warp-level HMMA, bf16x3 split, fp32 accum.
//  NEW tile shape to fix the measured smem-crossbar bound (LDSM wf : HMMA
//  was 1:1; now 0.67):
//  grid (272, 2) x 256 threads.  CTA (pid, jq): M=128 pair rows, N=256 half.
//  Warp grid 2m x 4n -> warp tile 64x64 (32 m16n8 frags, 128 acc regs).
//  K=512 in 8 chunks of 64, cp.async 2-stage double buffer (221 KB smem).
//  3 passes (hh, hl, lh) each sweeping all 32 accumulators.
// ---------------------------------------------------------------------------
#define KPB  144
#define AHI_OFF  0
#define ALO_OFF  18432
#define BHI_OFF  36864
#define BLO_OFF  73728
#define STAGE_SZ 110592

__global__ void __launch_bounds__(256, 1) k_mma(const int*   __restrict__ cat_ids,
                                                const float* __restrict__ b3,
                                                float*       __restrict__ out)
{
    extern __shared__ __align__(16) char smem[];

    const int pid = blockIdx.x;
    const int jq  = blockIdx.y;            // 0..1 (256-col half)
    if (pid >= g_npairs) return;

    const int2 pr = g_pairs[pid];
    const int b0  = pr.x;
    const int b1  = (pr.y < 0) ? pr.x : pr.y;
    const bool has_b1 = (pr.y >= 0);
    const int e   = cat_ids[b0];

    const int tid  = threadIdx.x;
    const int wid  = tid >> 5;
    const int lane = tid & 31;
    const int wm   = wid & 1;    // 2 m-strips of 64
    const int wn   = wid >> 1;   // 4 n-strips of 64

    const __nv_bfloat16* yh = g_yhi;
    const __nv_bfloat16* yl = g_ylo;
    const __nv_bfloat16* wh = g_w3hi + ((size_t)e * H_ + jq * 256) * H_;
    const __nv_bfloat16* wl = g_w3lo + ((size_t)e * H_ + jq * 256) * H_;

    const uint32_t sb = smem_u32(smem);

    // per-lane ldmatrix offsets
    const uint32_t arow  = (lane & 7) | (((lane >> 3) & 1) << 3);
    const uint32_t aoff  = (wm * 64 + arow) * KPB + (lane >> 4) * 16;
    const uint32_t nrow  = (lane & 7) | (((lane >> 4) & 1) << 3);
    const uint32_t boff  = (wn * 64 + nrow) * KPB + ((lane >> 3) & 1) * 16;

    #define LOADCHUNK(kc, p) do {                                               \
        char* _d = smem + (p) * STAGE_SZ;                                       \
        _Pragma("unroll")                                                       \
        for (int _l = 0; _l < 4; _l++) {                                        \
            int _i = tid + _l * 256;                                            \
            int _row = _i >> 3, _k8 = _i & 7;                                   \
            uint32_t _off = _row * KPB + _k8 * 16;                              \
            size_t _g = ((size_t)(((_row < 64) ? b0 : b1) * 64 + (_row & 63))) * 512 \
                        + (kc) * 64 + _k8 * 8;                                  \
            cp16(_d + AHI_OFF + _off, yh + _g);                                 \
            cp16(_d + ALO_OFF + _off, yl + _g);                                 \
        }                                                                       \
        _Pragma("unroll")                                                       \
        for (int _l = 0; _l < 8; _l++) {                                        \
            int _i = tid + _l * 256;                                            \
            int _n = _i >> 3, _k8 = _i & 7;                                     \
            uint32_t _off = _n * KPB + _k8 * 16;                                \
            size_t _g = (size_t)_n * 512 + (kc) * 64 + _k8 * 8;                 \
            cp16(_d + BHI_OFF + _off, wh + _g);                                 \
            cp16(_d + BLO_OFF + _off, wl + _g);                                 \
        }                                                                       \
        cp_commit();                                                            \
    } while (0)

    float acc[4][8][4];
    #pragma unroll
    for (int mt = 0; mt < 4; mt++)
        #pragma unroll
        for (int nt = 0; nt < 8; nt++)
            #pragma unroll
            for (int q = 0; q < 4; q++) acc[mt][nt][q] = 0.0f;

    LOADCHUNK(0, 0);

    for (int kc = 0; kc < 8; kc++) {
        cp_wait0();
        __syncthreads();
        if (kc < 7) LOADCHUNK(kc + 1, (kc + 1) & 1);

        const uint32_t stg = sb + (kc & 1) * STAGE_SZ;
        #pragma unroll
        for (int ks = 0; ks < 4; ks++) {
            const uint32_t kb = ks * 32;  // 16 bf16 = 32 bytes per k-step
            uint32_t ah[4][4], al[4][4], bh[4][4], bl[4][4];

            #pragma unroll
            for (int mt = 0; mt < 4; mt++)
                ldsm4(ah[mt], stg + aoff + mt * (16 * KPB) + kb + AHI_OFF);
            #pragma unroll
            for (int ng = 0; ng < 4; ng++)
                ldsm4(bh[ng], stg + boff + ng * (16 * KPB) + kb + BHI_OFF);

            // pass 1: hi * hi  (32 distinct accumulators)
            #pragma unroll
            for (int ng = 0; ng < 4; ng++)
                #pragma unroll
                for (int mt = 0; mt < 4; mt++) {
                    mma16816(acc[mt][2 * ng],     ah[mt], bh[ng][0], bh[ng][1]);
                    mma16816(acc[mt][2 * ng + 1], ah[mt], bh[ng][2], bh[ng][3]);
                }

            #pragma unroll
            for (int ng = 0; ng < 4; ng++)
                ldsm4(bl[ng], stg + boff + ng * (16 * KPB) + kb + BLO_OFF);

            // pass 2: hi * lo
            #pragma unroll
            for (int ng = 0; ng < 4; ng++)
                #pragma unroll
                for (int mt = 0; mt < 4; mt++) {
                    mma16816(acc[mt][2 * ng],     ah[mt], bl[ng][0], bl[ng][1]);
                    mma16816(acc[mt][2 * ng + 1], ah[mt], bl[ng][2], bl[ng][3]);
                }

            #pragma unroll
            for (int mt = 0; mt < 4; mt++)
                ldsm4(al[mt], stg + aoff + mt * (16 * KPB) + kb + ALO_OFF);

            // pass 3: lo * hi
            #pragma unroll
            for (int ng = 0; ng < 4; ng++)
                #pragma unroll
                for (int mt = 0; mt < 4; mt++) {
                    mma16816(acc[mt][2 * ng],     al[mt], bh[ng][0], bh[ng][1]);
                    mma16816(acc[mt][2 * ng + 1], al[mt], bh[ng][2], bh[ng][3]);
                }
        }
    }

    // epilogue: c frag (m16n8): thread t -> rows {t/4, t/4+8}, cols {2(t%4), +1}
    // wm=0 -> rows 0..63 (b0); wm=1 -> rows 64..127 (b1)
    {
        const int rgrp = lane >> 2;
        const int cgrp = 2 * (lane & 3);
        const float* b3e = b3 + e * H_;
        const int bsel = wm ? b1 : b0;
        if (wm == 0 || has_b1) {
            #pragma unroll
            for (int mt = 0; mt < 4; mt++) {
                const int r0 = mt * 16 + rgrp;                 // 0..63 local
                #pragma unroll
                for (int half = 0; half < 2; half++) {
                    const int r = r0 + half * 8;
                    float* outr = out + ((size_t)bsel * 64 + r) * 512;
                    #pragma unroll
                    for (int nt = 0; nt < 8; nt++) {
                        const int col = jq * 256 + wn * 64 + nt * 8 + cgrp;
                        float2 o;
                        o.x = acc[mt][nt][half * 2 + 0] + b3e[col];
                        o.y = acc[mt][nt][half * 2 + 1] + b3e[col + 1];
                        *(float2*)&outr[col] = o;
                    }
                }
            }
        }
    }
    #undef LOADCHUNK
}

// ---------------------------------------------------------------------------
extern "C" void kernel_launch(void* const* d_in, const int* in_sizes, int n_in,
                              void* d_out, int out_size)
{
    const float* actions = (const float*)d_in[0];
    const float* ts      = (const float*)d_in[1];
    const int*   cat     = (const int*)  d_in[2];
    const float* W1      = (const float*)d_in[3];
    const float* b1      = (const float*)d_in[4];
    const float* W2      = (const float*)d_in[5];
    const float* b2      = (const float*)d_in[6];
    const float* W3      = (const float*)d_in[7];
    const float* b3      = (const float*)d_in[8];
    float*       out     = (float*)d_out;

    const int smem_prep = (256 * 34 + 2 * 32 * 256) * 4;   // ~100 KB
    const int smem_y    = (32 * 256 + 64 * 32) * 4;        //  40 KB
    const int smem_mma  = 2 * STAGE_SZ;                    // 221184 B

    cudaFuncSetAttribute(k_prep, cudaFuncAttributeMaxDynamicSharedMemorySize, smem_prep);
    cudaFuncSetAttribute(k_y,    cudaFuncAttributeMaxDynamicSharedMemorySize, smem_y);
    cudaFuncSetAttribute(k_mma,  cudaFuncAttributeMaxDynamicSharedMemorySize, smem_mma);

    k_prep<<<769, 256, smem_prep>>>(ts, cat, W1, b1, W2, b2, W3);
    k_red <<<384, 512>>>();
    k_y   <<<dim3(B_, 2), 512, smem_y>>>(actions, cat);
    k_mma <<<dim3(272, 2), 256, smem_mma>>>(cat, b3, out);
}

// round 14
// speedup vs baseline: 1.2459x; 1.1369x over previous
#include <cuda_runtime.h>
#include <cuda_bf16.h>
#include <cuda_fp16.h>
#include <stdint.h>
#include <math.h>

#define B_ 512
#define T_ 64
#define A_ 32
#define H_ 512
#define E_ 32

typedef unsigned long long u64;

// scratch (device globals; allocation forbidden)
__device__ float g_M1[E_ * 64 * H_];          // split-K partials of W1@W2_top
__device__ float g_M1r[E_ * 32 * H_];         // reduced M1 (E,32,512)
__device__ float g_V2[2][B_ * H_];            // split-K partials of bias
__device__ float g_V[B_ * H_];                // reduced bias (B,512)
__device__ __half g_yh[B_ * T_ * H_];         // layer-1 output fp16 hi split
__device__ __half g_yl[B_ * T_ * H_];         // layer-1 output fp16 lo split
__device__ __half g_w3h[(size_t)E_ * H_ * H_]; // W3^T fp16 (single round) [e][n][k]
__device__ int2 g_pairs[272];
__device__ int  g_npairs;

#define DEV __device__ __forceinline__

DEV u64 pack2(float x) { u64 r; asm("mov.b64 %0, {%1, %1};" : "=l"(r) : "f"(x)); return r; }
DEV void fma2(u64 &d, u64 a, u64 b) { asm("fma.rn.f32x2 %0, %1, %2, %0;" : "+l"(d) : "l"(a), "l"(b)); }
DEV float2 unpk(u64 a) { float2 f; asm("mov.b64 {%0, %1}, %2;" : "=f"(f.x), "=f"(f.y) : "l"(a)); return f; }

DEV void cp16(void* dst, const void* src) {
    unsigned d = (unsigned)__cvta_generic_to_shared(dst);
    asm volatile("cp.async.cg.shared.global [%0], [%1], 16;" :: "r"(d), "l"(src));
}
DEV void cp_commit() { asm volatile("cp.async.commit_group;"); }
DEV void cp_wait0()  { asm volatile("cp.async.wait_group 0;"); }

union F4 { float4 v; float f[4]; u64 u[2]; };

DEV float swishf(float z) { return z / (1.0f + expf(-z)); }

DEV uint32_t smem_u32(const void* p) {
    uint32_t a;
    asm("{ .reg .u64 t; cvta.to.shared.u64 t, %1; cvt.u32.u64 %0, t; }" : "=r"(a) : "l"(p));
    return a;
}

DEV void ldsm4(uint32_t* r, uint32_t a) {
    asm volatile("ldmatrix.sync.aligned.m8n8.x4.shared.b16 {%0,%1,%2,%3}, [%4];"
                 : "=r"(r[0]), "=r"(r[1]), "=r"(r[2]), "=r"(r[3]) : "r"(a));
}
DEV void mma16816(float* c, const uint32_t* a, uint32_t b0, uint32_t b1) {
    asm volatile("mma.sync.aligned.m16n8k16.row.col.f32.f16.f16.f32 "
                 "{%0,%1,%2,%3}, {%4,%5,%6,%7}, {%8,%9}, {%0,%1,%2,%3};"
                 : "+f"(c[0]), "+f"(c[1]), "+f"(c[2]), "+f"(c[3])
                 : "r"(a[0]), "r"(a[1]), "r"(a[2]), "r"(a[3]), "r"(b0), "r"(b1));
}

// ---------------------------------------------------------------------------
// k_prep: 769 CTAs x 256 threads (R8 structure — measured best)
//   [0,128)    M1 split-K partial      (e = cid>>2, j-half, k-half)
//   [128,256)  V split-K partial
//   [256,768)  W3 -> transposed fp16 (4 64x64 tiles per CTA)
//   768        pair list (1 warp)
// ---------------------------------------------------------------------------
__global__ void __launch_bounds__(256) k_prep(const float* __restrict__ ts,
                                              const int*   __restrict__ cat,
                                              const float* __restrict__ W1,
                                              const float* __restrict__ b1,
                                              const float* __restrict__ W2,
                                              const float* __restrict__ b2,
                                              const float* __restrict__ W3)
{
    extern __shared__ float sm[];
    const int cid = blockIdx.x;
    const int tid = threadIdx.x;

    if (cid < 128) {
        // ---------------- M1 partial ----------------
        const int e  = cid >> 2;
        const int j0 = ((cid >> 1) & 1) * 256;
        const int kz = cid & 1;
        const int j  = j0 + tid;

        float* w1t = sm;                 // [256 hh][34]
        float* wt  = sm + 256 * 34;      // 2 x [32][256]

        const float* W1e = W1 + e * (A_ * H_);
        const float* W2h = W2 + e * (2 * H_ * H_) + kz * 256 * H_ + j0;

        #pragma unroll
        for (int l = 0; l < 8; l++) {
            int i = tid + l * 256;
            int r = i >> 6, c4 = (i & 63) << 2;
            cp16(wt + r * 256 + c4, W2h + r * H_ + c4);
        }
        cp_commit();

        for (int i = tid; i < 32 * 256; i += 256) {
            int a = i >> 8, hh = i & 255;
            w1t[hh * 34 + a] = W1e[a * H_ + kz * 256 + hh];
        }

        u64 acc[16];
        #pragma unroll
        for (int p = 0; p < 16; p++) acc[p] = 0ULL;

        for (int kt = 0; kt < 8; kt++) {
            cp_wait0();
            __syncthreads();
            if (kt < 7) {
                const float* src = W2h + (kt + 1) * 32 * H_;
                float* dst = wt + ((kt + 1) & 1) * (32 * 256);
                #pragma unroll
                for (int l = 0; l < 8; l++) {
                    int i = tid + l * 256;
                    int r = i >> 6, c4 = (i & 63) << 2;
                    cp16(dst + r * 256 + c4, src + r * H_ + c4);
                }
                cp_commit();
            }
            const float* cur = wt + (kt & 1) * (32 * 256);
            #pragma unroll 2
            for (int hl = 0; hl < 32; hl++) {
                const int hh = kt * 32 + hl;
                u64 wd = pack2(cur[hl * 256 + tid]);
                #pragma unroll
                for (int p = 0; p < 16; p++)
                    fma2(acc[p], *(const u64*)&w1t[hh * 34 + 2 * p], wd);
            }
        }
        float* M1e = g_M1 + e * (64 * H_) + kz * 32 * H_;
        #pragma unroll
        for (int p = 0; p < 16; p++) {
            float2 f = unpk(acc[p]);
            M1e[(2 * p) * H_ + j]     = f.x;
            M1e[(2 * p + 1) * H_ + j] = f.y;
        }
    } else if (cid < 256) {
        // ---------------- V partial ----------------
        const int vc = cid - 128;
        const int e  = vc >> 2;
        const int j0 = ((vc >> 1) & 1) * 256;
        const int kz = vc & 1;
        const int j  = j0 + tid;

        float* trig = sm;                         // [256 k][16 b]
        float* wt   = sm + 256 * 16;              // 2 x [32][256]
        int*   list = (int*)(sm + 256 * 16 + 2 * 32 * 256);
        int*   pn   = list + B_;

        if (tid == 0) *pn = 0;
        __syncthreads();
        for (int b = tid; b < B_; b += 256)
            if (cat[b] == e) { int p = atomicAdd(pn, 1); list[p] = b; }

        int nzl = (b1[e * H_ + kz * 256 + tid] != 0.0f);
        const int nz = __syncthreads_or(nzl);
        const int nb = *pn;

        const float* W2e = W2 + e * (2 * H_ * H_);
        float cb = (kz == 0) ? b2[e * H_ + j] : 0.0f;
        if (nz) {
            #pragma unroll 8
            for (int h = 0; h < 256; h++)
                cb += b1[e * H_ + kz * 256 + h] * W2e[(kz * 256 + h) * H_ + j];
        }

        const float L = 9.210340371976184f / 256.0f;
        const float* W2bot = W2e + H_ * H_ + kz * 256 * H_ + j0;

        for (int bg = 0; bg * 16 < nb; bg++) {
            const int m = min(16, nb - bg * 16);
            __syncthreads();
            for (int i = tid; i < 16 * 256; i += 256) {
                int k = i >> 4, q = i & 15;
                float t = (q < m) ? ts[list[bg * 16 + q]] : 0.0f;
                float ang = t * expf(-L * (float)k);
                trig[k * 16 + q] = kz ? cosf(ang) : sinf(ang);
            }
            #pragma unroll
            for (int l = 0; l < 8; l++) {
                int i = tid + l * 256;
                int r = i >> 6, c4 = (i & 63) << 2;
                cp16(wt + r * 256 + c4, W2bot + r * H_ + c4);
            }
            cp_commit();

            u64 acc[8];
            #pragma unroll
            for (int q = 0; q < 8; q++) acc[q] = 0ULL;

            for (int kt = 0; kt < 8; kt++) {
                cp_wait0();
                __syncthreads();
                if (kt < 7) {
                    const float* src = W2bot + (kt + 1) * 32 * H_;
                    float* dst = wt + ((kt + 1) & 1) * (32 * 256);
                    #pragma unroll
                    for (int l = 0; l < 8; l++) {
                        int i = tid + l * 256;
                        int r = i >> 6, c4 = (i & 63) << 2;
                        cp16(dst + r * 256 + c4, src + r * H_ + c4);
                    }
                    cp_commit();
                }
                const float* cur = wt + (kt & 1) * (32 * 256);
                #pragma unroll 2
                for (int kk = 0; kk < 32; kk++) {
                    const int k = kt * 32 + kk;
                    u64 wd = pack2(cur[kk * 256 + tid]);
                    #pragma unroll
                    for (int q = 0; q < 8; q++)
                        fma2(acc[q], *(const u64*)&trig[k * 16 + 2 * q], wd);
                }
            }
            #pragma unroll
            for (int q = 0; q < 8; q++) {
                float2 f = unpk(acc[q]);
                if (2 * q < m)     g_V2[kz][list[bg * 16 + 2 * q] * H_ + j]     = f.x + cb;
                if (2 * q + 1 < m) g_V2[kz][list[bg * 16 + 2 * q + 1] * H_ + j] = f.y + cb;
            }
        }
    } else if (cid < 768) {
        // -------- W3 transpose + fp16 round (4 tiles; single output array) ----
        float (*tile)[65] = (float(*)[65])sm;     // [64][65]
        const int wc = cid - 256;                 // 0..511
        const int e  = wc >> 4;
        const int tbase = (wc & 15) * 4;
        #pragma unroll
        for (int ti = 0; ti < 4; ti++) {
            const int t  = tbase + ti;            // 0..63
            const int kb = (t >> 3) * 64;
            const int nb = (t & 7) * 64;
            const float* src = W3 + ((size_t)e * H_ + kb) * H_ + nb;
            __syncthreads();
            #pragma unroll
            for (int l = 0; l < 16; l++) {
                int i = tid + l * 256;
                int r = i >> 6, c = i & 63;
                tile[r][c] = src[(size_t)r * H_ + c];
            }
            __syncthreads();
            #pragma unroll
            for (int l = 0; l < 16; l++) {
                int i = tid + l * 256;
                int r = i >> 6, c = i & 63;        // r = n-local, c = k-local
                size_t o = ((size_t)e * H_ + nb + r) * H_ + kb + c;
                g_w3h[o] = __float2half_rn(tile[c][r]);
            }
        }
    } else {
        // ---------------- pair list (1 warp) ----------------
        if (tid < 32) {
            const int e = tid;
            if (e == 0) g_npairs = 0;
            __syncwarp();
            int prev = -1;
            for (int b = 0; b < B_; b++) {
                if (cat[b] == e) {
                    if (prev < 0) prev = b;
                    else {
                        int p = atomicAdd(&g_npairs, 1);
                        g_pairs[p] = make_int2(prev, b);
                        prev = -1;
                    }
                }
            }
            if (prev >= 0) {
                int p = atomicAdd(&g_npairs, 1);
                g_pairs[p] = make_int2(prev, -1);
            }
        }
    }
}

// ---------------------------------------------------------------------------
// k_red: fold split-K partials (R8 version, measured 5.4 us)
// ---------------------------------------------------------------------------
__global__ void __launch_bounds__(512) k_red()
{
    const int i = blockIdx.x * 512 + threadIdx.x;
    const float4* m1 = (const float4*)g_M1;
    if (i < 131072) {
        int e = i >> 12, r = i & 4095;
        F4 a, b;
        a.v = m1[e * 8192 + r];
        b.v = m1[e * 8192 + 4096 + r];
        #pragma unroll
        for (int q = 0; q < 4; q++) a.f[q] += b.f[q];
        ((float4*)g_M1r)[i] = a.v;
    } else {
        int r = i - 131072;
        F4 a, b;
        a.v = ((const float4*)g_V2[0])[r];
        b.v = ((const float4*)g_V2[1])[r];
        #pragma unroll
        for (int q = 0; q < 4; q++) a.f[q] += b.f[q];
        ((float4*)g_V)[r] = a.v;
    }
}

// ---------------------------------------------------------------------------
// k_y helpers (SIMT layer-1)
// ---------------------------------------------------------------------------
template <int NK4>
DEV void mma4(const float* __restrict__ wb, const float* __restrict__ yrow,
              int ystride, u64 (&acc)[4][4], int t0, int jb)
{
    #pragma unroll
    for (int k4 = 0; k4 < NK4; k4++) {
        F4 yv[4];
        #pragma unroll
        for (int r = 0; r < 4; r++)
            yv[r].v = *(const float4*)&yrow[(t0 + r) * ystride + k4 * 4];
        #pragma unroll
        for (int kk = 0; kk < 4; kk++) {
            F4 w0, w1;
            w0.v = *(const float4*)&wb[(k4 * 4 + kk) * 256 + jb];
            w1.v = *(const float4*)&wb[(k4 * 4 + kk) * 256 + jb + 128];
            #pragma unroll
            for (int r = 0; r < 4; r++) {
                u64 yd = pack2(yv[r].f[kk]);
                fma2(acc[r][0], yd, w0.u[0]);
                fma2(acc[r][1], yd, w0.u[1]);
                fma2(acc[r][2], yd, w1.u[0]);
                fma2(acc[r][3], yd, w1.u[1]);
            }
        }
    }
}

// ---------------------------------------------------------------------------
// k_y: y = swish(actions @ M1r + v), split to fp16 hi/lo.  grid (B,2) x 512
// ---------------------------------------------------------------------------
__global__ void __launch_bounds__(512) k_y(const float* __restrict__ actions,
                                           const int*   __restrict__ cat_ids)
{
    extern __shared__ float sm[];
    float* m1  = sm;              // [32][256]
    float* act = sm + 32 * 256;   // [64][32]

    const int tid = threadIdx.x;
    const int b   = blockIdx.x;
    const int jh  = blockIdx.y;
    const int e   = cat_ids[b];
    const int t0  = (tid >> 5) * 4;
    const int jb  = (tid & 31) * 4;

    const float* M1e  = g_M1r + e * (32 * H_) + jh * 256;
    const float* actb = actions + b * (T_ * A_);

    #pragma unroll
    for (int l = 0; l < 4; l++) {
        int i = tid + l * 512;
        int r = i >> 6, c4 = (i & 63) << 2;
        cp16(m1 + r * 256 + c4, M1e + (size_t)r * H_ + c4);
    }
    cp16(act + tid * 4, actb + tid * 4);
    cp_commit();
    cp_wait0();
    __syncthreads();

    u64 acc[4][4];
    #pragma unroll
    for (int r = 0; r < 4; r++)
        #pragma unroll
        for (int c = 0; c < 4; c++) acc[r][c] = 0ULL;

    mma4<4>(m1,            act,      32, acc, t0, jb);
    mma4<4>(m1 + 16 * 256, act + 16, 32, acc, t0, jb);

    const float* vp = g_V + b * H_ + jh * 256;
    F4 v0, v1;
    v0.v = *(const float4*)&vp[jb];
    v1.v = *(const float4*)&vp[jb + 128];

    #pragma unroll
    for (int r = 0; r < 4; r++) {
        float y[8];
        float2 a0 = unpk(acc[r][0]), a1 = unpk(acc[r][1]);
        float2 a2 = unpk(acc[r][2]), a3 = unpk(acc[r][3]);
        y[0] = swishf(a0.x + v0.f[0]); y[1] = swishf(a0.y + v0.f[1]);
        y[2] = swishf(a1.x + v0.f[2]); y[3] = swishf(a1.y + v0.f[3]);
        y[4] = swishf(a2.x + v1.f[0]); y[5] = swishf(a2.y + v1.f[1]);
        y[6] = swishf(a3.x + v1.f[2]); y[7] = swishf(a3.y + v1.f[3]);

        __half hi[8], lo[8];
        #pragma unroll
        for (int q = 0; q < 8; q++) {
            hi[q] = __float2half_rn(y[q]);
            lo[q] = __float2half_rn(y[q] - __half2float(hi[q]));
        }
        size_t base = ((size_t)b * 64 + t0 + r) * 512 + jh * 256;
        *(uint2*)&g_yh[base + jb]       = *(uint2*)&hi[0];
        *(uint2*)&g_yh[base + jb + 128] = *(uint2*)&hi[4];
        *(uint2*)&g_yl[base + jb]       = *(uint2*)&lo[0];
        *(uint2*)&g_yl[base + jb + 128] = *(uint2*)&lo[4];
    }
}

// ---------------------------------------------------------------------------
// k_mma: layer 2 on warp-level HMMA, fp16x2 split (yh*W + yl*W), fp32 accum.
//  R8 geometry (measured best): grid (272, 4) x 256 threads.
//  CTA (pid, jq): M=128 pair rows, N=128 quarter; warp grid 4m x 2n ->
//  warp tile 32x64, 16 frag accumulators.
//  K=512 in 8 chunks of 64, cp.async 2-stage double buffer.
//  Per k-step: 2 passes (yh*W, yl*W) each sweeping all 16 accumulators —
//  33% fewer MMAs and 33% fewer LDSM than the bf16x3 version.
// ---------------------------------------------------------------------------
#define KPB  144
#define AHI_OFF  0
#define ALO_OFF  18432
#define BH_OFF   36864
#define STAGE_SZ 55296

__global__ void __launch_bounds__(256, 1) k_mma(const int*   __restrict__ cat_ids,
                                                const float* __restrict__ b3,
                                                float*       __restrict__ out)
{
    extern __shared__ __align__(16) char smem[];

    const int pid = blockIdx.x;
    const int jq  = blockIdx.y;
    if (pid >= g_npairs) return;

    const int2 pr = g_pairs[pid];
    const int b0  = pr.x;
    const int b1  = (pr.y < 0) ? pr.x : pr.y;
    const bool has_b1 = (pr.y >= 0);
    const int e   = cat_ids[b0];

    const int tid  = threadIdx.x;
    const int wid  = tid >> 5;
    const int lane = tid & 31;
    const int wm   = wid & 3;    // 4 m-strips of 32
    const int wn   = wid >> 2;   // 2 n-strips of 64

    const __half* yh = g_yh;
    const __half* yl = g_yl;
    const __half* wh = g_w3h + ((size_t)e * H_ + jq * 128) * H_;

    const uint32_t sb = smem_u32(smem);

    // per-lane ldmatrix offsets
    const uint32_t arow  = (lane & 7) | (((lane >> 3) & 1) << 3);
    const uint32_t aoff  = (wm * 32 + arow) * KPB + (lane >> 4) * 16;
    const uint32_t nrow  = (lane & 7) | (((lane >> 4) & 1) << 3);
    const uint32_t boff  = (wn * 64 + nrow) * KPB + ((lane >> 3) & 1) * 16;

    #define LOADCHUNK(kc, p) do {                                               \
        char* _d = smem + (p) * STAGE_SZ;                                       \
        _Pragma("unroll")                                                       \
        for (int _l = 0; _l < 4; _l++) {                                        \
            int _i = tid + _l * 256;                                            \
            int _row = _i >> 3, _k8 = _i & 7;                                   \
            uint32_t _off = _row * KPB + _k8 * 16;                              \
            size_t _g = ((size_t)(((_row < 64) ? b0 : b1) * 64 + (_row & 63))) * 512 \
                        + (kc) * 64 + _k8 * 8;                                  \
            cp16(_d + AHI_OFF + _off, yh + _g);                                 \
            cp16(_d + ALO_OFF + _off, yl + _g);                                 \
        }                                                                       \
        _Pragma("unroll")                                                       \
        for (int _l = 0; _l < 4; _l++) {                                        \
            int _i = tid + _l * 256;                                            \
            int _n = _i >> 3, _k8 = _i & 7;                                     \
            uint32_t _off = _n * KPB + _k8 * 16;                                \
            size_t _g = (size_t)_n * 512 + (kc) * 64 + _k8 * 8;                 \
            cp16(_d + BH_OFF + _off, wh + _g);                                  \
        }                                                                       \
        cp_commit();                                                            \
    } while (0)

    float acc[2][8][4];
    #pragma unroll
    for (int mt = 0; mt < 2; mt++)
        #pragma unroll
        for (int nt = 0; nt < 8; nt++)
            #pragma unroll
            for (int q = 0; q < 4; q++) acc[mt][nt][q] = 0.0f;

    LOADCHUNK(0, 0);

    for (int kc = 0; kc < 8; kc++) {
        cp_wait0();
        __syncthreads();
        if (kc < 7) LOADCHUNK(kc + 1, (kc + 1) & 1);

        const uint32_t stg = sb + (kc & 1) * STAGE_SZ;
        #pragma unroll
        for (int ks = 0; ks < 4; ks++) {
            const uint32_t kb = ks * 32;  // 16 fp16 = 32 bytes per k-step
            uint32_t ah[2][4], al[2][4], bh[4][4];

            #pragma unroll
            for (int mt = 0; mt < 2; mt++)
                ldsm4(ah[mt], stg + aoff + mt * (16 * KPB) + kb + AHI_OFF);
            #pragma unroll
            for (int nt = 0; nt < 4; nt++)
                ldsm4(bh[nt], stg + boff + nt * (16 * KPB) + kb + BH_OFF);

            // pass 1: yh * W  (16 distinct accumulators)
            #pragma unroll
            for (int nt = 0; nt < 4; nt++)
                #pragma unroll
                for (int mt = 0; mt < 2; mt++) {
                    mma16816(acc[mt][2 * nt],     ah[mt], bh[nt][0], bh[nt][1]);
                    mma16816(acc[mt][2 * nt + 1], ah[mt], bh[nt][2], bh[nt][3]);
                }

            #pragma unroll
            for (int mt = 0; mt < 2; mt++)
                ldsm4(al[mt], stg + aoff + mt * (16 * KPB) + kb + ALO_OFF);

            // pass 2: yl * W
            #pragma unroll
            for (int nt = 0; nt < 4; nt++)
                #pragma unroll
                for (int mt = 0; mt < 2; mt++) {
                    mma16816(acc[mt][2 * nt],     al[mt], bh[nt][0], bh[nt][1]);
                    mma16816(acc[mt][2 * nt + 1], al[mt], bh[nt][2], bh[nt][3]);
                }
        }
    }

    // epilogue: c frag (m16n8): thread t -> rows {t/4, t/4+8}, cols {2(t%4), +1}
    {
        const int rgrp = lane >> 2;
        const int cgrp = 2 * (lane & 3);
        const float* b3e = b3 + e * H_;
        #pragma unroll
        for (int mt = 0; mt < 2; mt++) {
            const int r0 = wm * 32 + mt * 16 + rgrp;       // 0..127
            #pragma unroll
            for (int half = 0; half < 2; half++) {
                const int r = r0 + half * 8;
                const int bsel = (r < 64) ? b0 : b1;
                if (r >= 64 && !has_b1) continue;
                float* outr = out + ((size_t)bsel * 64 + (r & 63)) * 512;
                #pragma unroll
                for (int nt = 0; nt < 8; nt++) {
                    const int col = jq * 128 + wn * 64 + nt * 8 + cgrp;
                    float2 o;
                    o.x = acc[mt][nt][half * 2 + 0] + b3e[col];
                    o.y = acc[mt][nt][half * 2 + 1] + b3e[col + 1];
                    *(float2*)&outr[col] = o;
                }
            }
        }
    }
    #undef LOADCHUNK
}

// ---------------------------------------------------------------------------
extern "C" void kernel_launch(void* const* d_in, const int* in_sizes, int n_in,
                              void* d_out, int out_size)
{
    const float* actions = (const float*)d_in[0];
    const float* ts      = (const float*)d_in[1];
    const int*   cat     = (const int*)  d_in[2];
    const float* W1      = (const float*)d_in[3];
    const float* b1      = (const float*)d_in[4];
    const float* W2      = (const float*)d_in[5];
    const float* b2      = (const float*)d_in[6];
    const float* W3      = (const float*)d_in[7];
    const float* b3      = (const float*)d_in[8];
    float*       out     = (float*)d_out;

    const int smem_prep = (256 * 34 + 2 * 32 * 256) * 4;   // ~100 KB
    const int smem_y    = (32 * 256 + 64 * 32) * 4;        //  40 KB
    const int smem_mma  = 2 * STAGE_SZ;                    // 108 KB

    cudaFuncSetAttribute(k_prep, cudaFuncAttributeMaxDynamicSharedMemorySize, smem_prep);
    cudaFuncSetAttribute(k_y,    cudaFuncAttributeMaxDynamicSharedMemorySize, smem_y);
    cudaFuncSetAttribute(k_mma,  cudaFuncAttributeMaxDynamicSharedMemorySize, smem_mma);

    k_prep<<<769, 256, smem_prep>>>(ts, cat, W1, b1, W2, b2, W3);
    k_red <<<384, 512>>>();
    k_y   <<<dim3(B_, 2), 512, smem_y>>>(actions, cat);
    k_mma <<<dim3(272, 4), 256, smem_mma>>>(cat, b3, out);
}

// round 15
// speedup vs baseline: 1.4551x; 1.1679x over previous
#include <cuda_runtime.h>
#include <cuda_bf16.h>
#include <cuda_fp16.h>
#include <stdint.h>
#include <math.h>

#define B_ 512
#define T_ 64
#define A_ 32
#define H_ 512
#define E_ 32

typedef unsigned long long u64;

// scratch (device globals; allocation forbidden)
__device__ float g_M1[E_ * 64 * H_];          // split-K partials of W1@W2_top
__device__ float g_M1r[E_ * 32 * H_];         // reduced M1 (E,32,512)
__device__ float g_V2[2][B_ * H_];            // split-K partials of bias
__device__ float g_V[B_ * H_];                // reduced bias (B,512)
__device__ __half g_yh[B_ * T_ * H_];         // layer-1 output fp16 [b*64+t][k]
__device__ __half g_w3h[(size_t)E_ * H_ * H_]; // W3^T fp16 [e][n][k]
__device__ int2 g_pairs[272];
__device__ int  g_npairs;

#define DEV __device__ __forceinline__

DEV u64 pack2(float x) { u64 r; asm("mov.b64 %0, {%1, %1};" : "=l"(r) : "f"(x)); return r; }
DEV void fma2(u64 &d, u64 a, u64 b) { asm("fma.rn.f32x2 %0, %1, %2, %0;" : "+l"(d) : "l"(a), "l"(b)); }
DEV float2 unpk(u64 a) { float2 f; asm("mov.b64 {%0, %1}, %2;" : "=f"(f.x), "=f"(f.y) : "l"(a)); return f; }

DEV void cp16(void* dst, const void* src) {
    unsigned d = (unsigned)__cvta_generic_to_shared(dst);
    asm volatile("cp.async.cg.shared.global [%0], [%1], 16;" :: "r"(d), "l"(src));
}
DEV void cp_commit() { asm volatile("cp.async.commit_group;"); }
DEV void cp_wait0()  { asm volatile("cp.async.wait_group 0;"); }

union F4 { float4 v; float f[4]; u64 u[2]; };

DEV float swishf(float z) { return z / (1.0f + expf(-z)); }

DEV uint32_t smem_u32(const void* p) {
    uint32_t a;
    asm("{ .reg .u64 t; cvta.to.shared.u64 t, %1; cvt.u32.u64 %0, t; }" : "=r"(a) : "l"(p));
    return a;
}

DEV void ldsm4(uint32_t* r, uint32_t a) {
    asm volatile("ldmatrix.sync.aligned.m8n8.x4.shared.b16 {%0,%1,%2,%3}, [%4];"
                 : "=r"(r[0]), "=r"(r[1]), "=r"(r[2]), "=r"(r[3]) : "r"(a));
}
DEV void mma16816(float* c, const uint32_t* a, uint32_t b0, uint32_t b1) {
    asm volatile("mma.sync.aligned.m16n8k16.row.col.f32.f16.f16.f32 "
                 "{%0,%1,%2,%3}, {%4,%5,%6,%7}, {%8,%9}, {%0,%1,%2,%3};"
                 : "+f"(c[0]), "+f"(c[1]), "+f"(c[2]), "+f"(c[3])
                 : "r"(a[0]), "r"(a[1]), "r"(a[2]), "r"(a[3]), "r"(b0), "r"(b1));
}

// ---------------------------------------------------------------------------
// k_prep: 769 CTAs x 256 threads (R14 version — measured best)
//   [0,128)    M1 split-K partial      (e = cid>>2, j-half, k-half)
//   [128,256)  V split-K partial
//   [256,768)  W3 -> transposed fp16 (4 64x64 tiles per CTA)
//   768        pair list (1 warp)
// ---------------------------------------------------------------------------
__global__ void __launch_bounds__(256) k_prep(const float* __restrict__ ts,
                                              const int*   __restrict__ cat,
                                              const float* __restrict__ W1,
                                              const float* __restrict__ b1,
                                              const float* __restrict__ W2,
                                              const float* __restrict__ b2,
                                              const float* __restrict__ W3)
{
    extern __shared__ float sm[];
    const int cid = blockIdx.x;
    const int tid = threadIdx.x;

    if (cid < 128) {
        // ---------------- M1 partial ----------------
        const int e  = cid >> 2;
        const int j0 = ((cid >> 1) & 1) * 256;
        const int kz = cid & 1;
        const int j  = j0 + tid;

        float* w1t = sm;                 // [256 hh][34]
        float* wt  = sm + 256 * 34;      // 2 x [32][256]

        const float* W1e = W1 + e * (A_ * H_);
        const float* W2h = W2 + e * (2 * H_ * H_) + kz * 256 * H_ + j0;

        #pragma unroll
        for (int l = 0; l < 8; l++) {
            int i = tid + l * 256;
            int r = i >> 6, c4 = (i & 63) << 2;
            cp16(wt + r * 256 + c4, W2h + r * H_ + c4);
        }
        cp_commit();

        for (int i = tid; i < 32 * 256; i += 256) {
            int a = i >> 8, hh = i & 255;
            w1t[hh * 34 + a] = W1e[a * H_ + kz * 256 + hh];
        }

        u64 acc[16];
        #pragma unroll
        for (int p = 0; p < 16; p++) acc[p] = 0ULL;

        for (int kt = 0; kt < 8; kt++) {
            cp_wait0();
            __syncthreads();
            if (kt < 7) {
                const float* src = W2h + (kt + 1) * 32 * H_;
                float* dst = wt + ((kt + 1) & 1) * (32 * 256);
                #pragma unroll
                for (int l = 0; l < 8; l++) {
                    int i = tid + l * 256;
                    int r = i >> 6, c4 = (i & 63) << 2;
                    cp16(dst + r * 256 + c4, src + r * H_ + c4);
                }
                cp_commit();
            }
            const float* cur = wt + (kt & 1) * (32 * 256);
            #pragma unroll 2
            for (int hl = 0; hl < 32; hl++) {
                const int hh = kt * 32 + hl;
                u64 wd = pack2(cur[hl * 256 + tid]);
                #pragma unroll
                for (int p = 0; p < 16; p++)
                    fma2(acc[p], *(const u64*)&w1t[hh * 34 + 2 * p], wd);
            }
        }
        float* M1e = g_M1 + e * (64 * H_) + kz * 32 * H_;
        #pragma unroll
        for (int p = 0; p < 16; p++) {
            float2 f = unpk(acc[p]);
            M1e[(2 * p) * H_ + j]     = f.x;
            M1e[(2 * p + 1) * H_ + j] = f.y;
        }
    } else if (cid < 256) {
        // ---------------- V partial ----------------
        const int vc = cid - 128;
        const int e  = vc >> 2;
        const int j0 = ((vc >> 1) & 1) * 256;
        const int kz = vc & 1;
        const int j  = j0 + tid;

        float* trig = sm;                         // [256 k][16 b]
        float* wt   = sm + 256 * 16;              // 2 x [32][256]
        int*   list = (int*)(sm + 256 * 16 + 2 * 32 * 256);
        int*   pn   = list + B_;

        if (tid == 0) *pn = 0;
        __syncthreads();
        for (int b = tid; b < B_; b += 256)
            if (cat[b] == e) { int p = atomicAdd(pn, 1); list[p] = b; }

        int nzl = (b1[e * H_ + kz * 256 + tid] != 0.0f);
        const int nz = __syncthreads_or(nzl);
        const int nb = *pn;

        const float* W2e = W2 + e * (2 * H_ * H_);
        float cb = (kz == 0) ? b2[e * H_ + j] : 0.0f;
        if (nz) {
            #pragma unroll 8
            for (int h = 0; h < 256; h++)
                cb += b1[e * H_ + kz * 256 + h] * W2e[(kz * 256 + h) * H_ + j];
        }

        const float L = 9.210340371976184f / 256.0f;
        const float* W2bot = W2e + H_ * H_ + kz * 256 * H_ + j0;

        for (int bg = 0; bg * 16 < nb; bg++) {
            const int m = min(16, nb - bg * 16);
            __syncthreads();
            for (int i = tid; i < 16 * 256; i += 256) {
                int k = i >> 4, q = i & 15;
                float t = (q < m) ? ts[list[bg * 16 + q]] : 0.0f;
                float ang = t * expf(-L * (float)k);
                trig[k * 16 + q] = kz ? cosf(ang) : sinf(ang);
            }
            #pragma unroll
            for (int l = 0; l < 8; l++) {
                int i = tid + l * 256;
                int r = i >> 6, c4 = (i & 63) << 2;
                cp16(wt + r * 256 + c4, W2bot + r * H_ + c4);
            }
            cp_commit();

            u64 acc[8];
            #pragma unroll
            for (int q = 0; q < 8; q++) acc[q] = 0ULL;

            for (int kt = 0; kt < 8; kt++) {
                cp_wait0();
                __syncthreads();
                if (kt < 7) {
                    const float* src = W2bot + (kt + 1) * 32 * H_;
                    float* dst = wt + ((kt + 1) & 1) * (32 * 256);
                    #pragma unroll
                    for (int l = 0; l < 8; l++) {
                        int i = tid + l * 256;
                        int r = i >> 6, c4 = (i & 63) << 2;
                        cp16(dst + r * 256 + c4, src + r * H_ + c4);
                    }
                    cp_commit();
                }
                const float* cur = wt + (kt & 1) * (32 * 256);
                #pragma unroll 2
                for (int kk = 0; kk < 32; kk++) {
                    const int k = kt * 32 + kk;
                    u64 wd = pack2(cur[kk * 256 + tid]);
                    #pragma unroll
                    for (int q = 0; q < 8; q++)
                        fma2(acc[q], *(const u64*)&trig[k * 16 + 2 * q], wd);
                }
            }
            #pragma unroll
            for (int q = 0; q < 8; q++) {
                float2 f = unpk(acc[q]);
                if (2 * q < m)     g_V2[kz][list[bg * 16 + 2 * q] * H_ + j]     = f.x + cb;
                if (2 * q + 1 < m) g_V2[kz][list[bg * 16 + 2 * q + 1] * H_ + j] = f.y + cb;
            }
        }
    } else if (cid < 768) {
        // -------- W3 transpose + fp16 round (4 tiles) --------
        float (*tile)[65] = (float(*)[65])sm;     // [64][65]
        const int wc = cid - 256;                 // 0..511
        const int e  = wc >> 4;
        const int tbase = (wc & 15) * 4;
        #pragma unroll
        for (int ti = 0; ti < 4; ti++) {
            const int t  = tbase + ti;            // 0..63
            const int kb = (t >> 3) * 64;
            const int nb = (t & 7) * 64;
            const float* src = W3 + ((size_t)e * H_ + kb) * H_ + nb;
            __syncthreads();
            #pragma unroll
            for (int l = 0; l < 16; l++) {
                int i = tid + l * 256;
                int r = i >> 6, c = i & 63;
                tile[r][c] = src[(size_t)r * H_ + c];
            }
            __syncthreads();
            #pragma unroll
            for (int l = 0; l < 16; l++) {
                int i = tid + l * 256;
                int r = i >> 6, c = i & 63;        // r = n-local, c = k-local
                size_t o = ((size_t)e * H_ + nb + r) * H_ + kb + c;
                g_w3h[o] = __float2half_rn(tile[c][r]);
            }
        }
    } else {
        // ---------------- pair list (1 warp) ----------------
        if (tid < 32) {
            const int e = tid;
            if (e == 0) g_npairs = 0;
            __syncwarp();
            int prev = -1;
            for (int b = 0; b < B_; b++) {
                if (cat[b] == e) {
                    if (prev < 0) prev = b;
                    else {
                        int p = atomicAdd(&g_npairs, 1);
                        g_pairs[p] = make_int2(prev, b);
                        prev = -1;
                    }
                }
            }
            if (prev >= 0) {
                int p = atomicAdd(&g_npairs, 1);
                g_pairs[p] = make_int2(prev, -1);
            }
        }
    }
}

// ---------------------------------------------------------------------------
// k_red: fold split-K partials (R8 version, measured 5.4 us)
// ---------------------------------------------------------------------------
__global__ void __launch_bounds__(512) k_red()
{
    const int i = blockIdx.x * 512 + threadIdx.x;
    const float4* m1 = (const float4*)g_M1;
    if (i < 131072) {
        int e = i >> 12, r = i & 4095;
        F4 a, b;
        a.v = m1[e * 8192 + r];
        b.v = m1[e * 8192 + 4096 + r];
        #pragma unroll
        for (int q = 0; q < 4; q++) a.f[q] += b.f[q];
        ((float4*)g_M1r)[i] = a.v;
    } else {
        int r = i - 131072;
        F4 a, b;
        a.v = ((const float4*)g_V2[0])[r];
        b.v = ((const float4*)g_V2[1])[r];
        #pragma unroll
        for (int q = 0; q < 4; q++) a.f[q] += b.f[q];
        ((float4*)g_V)[r] = a.v;
    }
}

// ---------------------------------------------------------------------------
// k_y helpers (SIMT layer-1)
// ---------------------------------------------------------------------------
template <int NK4>
DEV void mma4(const float* __restrict__ wb, const float* __restrict__ yrow,
              int ystride, u64 (&acc)[4][4], int t0, int jb)
{
    #pragma unroll
    for (int k4 = 0; k4 < NK4; k4++) {
        F4 yv[4];
        #pragma unroll
        for (int r = 0; r < 4; r++)
            yv[r].v = *(const float4*)&yrow[(t0 + r) * ystride + k4 * 4];
        #pragma unroll
        for (int kk = 0; kk < 4; kk++) {
            F4 w0, w1;
            w0.v = *(const float4*)&wb[(k4 * 4 + kk) * 256 + jb];
            w1.v = *(const float4*)&wb[(k4 * 4 + kk) * 256 + jb + 128];
            #pragma unroll
            for (int r = 0; r < 4; r++) {
                u64 yd = pack2(yv[r].f[kk]);
                fma2(acc[r][0], yd, w0.u[0]);
                fma2(acc[r][1], yd, w0.u[1]);
                fma2(acc[r][2], yd, w1.u[0]);
                fma2(acc[r][3], yd, w1.u[1]);
            }
        }
    }
}

// ---------------------------------------------------------------------------
// k_y: y = swish(actions @ M1r + v), rounded once to fp16.  grid (B,2) x 512
// ---------------------------------------------------------------------------
__global__ void __launch_bounds__(512) k_y(const float* __restrict__ actions,
                                           const int*   __restrict__ cat_ids)
{
    extern __shared__ float sm[];
    float* m1  = sm;              // [32][256]
    float* act = sm + 32 * 256;   // [64][32]

    const int tid = threadIdx.x;
    const int b   = blockIdx.x;
    const int jh  = blockIdx.y;
    const int e   = cat_ids[b];
    const int t0  = (tid >> 5) * 4;
    const int jb  = (tid & 31) * 4;

    const float* M1e  = g_M1r + e * (32 * H_) + jh * 256;
    const float* actb = actions + b * (T_ * A_);

    #pragma unroll
    for (int l = 0; l < 4; l++) {
        int i = tid + l * 512;
        int r = i >> 6, c4 = (i & 63) << 2;
        cp16(m1 + r * 256 + c4, M1e + (size_t)r * H_ + c4);
    }
    cp16(act + tid * 4, actb + tid * 4);
    cp_commit();
    cp_wait0();
    __syncthreads();

    u64 acc[4][4];
    #pragma unroll
    for (int r = 0; r < 4; r++)
        #pragma unroll
        for (int c = 0; c < 4; c++) acc[r][c] = 0ULL;

    mma4<4>(m1,            act,      32, acc, t0, jb);
    mma4<4>(m1 + 16 * 256, act + 16, 32, acc, t0, jb);

    const float* vp = g_V + b * H_ + jh * 256;
    F4 v0, v1;
    v0.v = *(const float4*)&vp[jb];
    v1.v = *(const float4*)&vp[jb + 128];

    #pragma unroll
    for (int r = 0; r < 4; r++) {
        float y[8];
        float2 a0 = unpk(acc[r][0]), a1 = unpk(acc[r][1]);
        float2 a2 = unpk(acc[r][2]), a3 = unpk(acc[r][3]);
        y[0] = swishf(a0.x + v0.f[0]); y[1] = swishf(a0.y + v0.f[1]);
        y[2] = swishf(a1.x + v0.f[2]); y[3] = swishf(a1.y + v0.f[3]);
        y[4] = swishf(a2.x + v1.f[0]); y[5] = swishf(a2.y + v1.f[1]);
        y[6] = swishf(a3.x + v1.f[2]); y[7] = swishf(a3.y + v1.f[3]);

        __half hi[8];
        #pragma unroll
        for (int q = 0; q < 8; q++)
            hi[q] = __float2half_rn(y[q]);
        size_t base = ((size_t)b * 64 + t0 + r) * 512 + jh * 256;
        *(uint2*)&g_yh[base + jb]       = *(uint2*)&hi[0];
        *(uint2*)&g_yh[base + jb + 128] = *(uint2*)&hi[4];
    }
}

// ---------------------------------------------------------------------------
// k_mma: layer 2 on warp-level HMMA, PURE fp16 (single pass), fp32 accum.
//  R8 geometry: grid (272, 4) x 256 threads.
//  CTA (pid, jq): M=128 pair rows, N=128 quarter; warp grid 4m x 2n ->
//  warp tile 32x64, 16 frag accumulators.
//  K=512 in 8 chunks of 64, cp.async 2-stage double buffer (72 KB smem).
//  Per k-step: 1 pass (y*W) sweeping all 16 accumulators — half the MMAs
//  and 3/4 of the LDSM wavefronts of the fp16x2 version.
// ---------------------------------------------------------------------------
#define KPB  144
#define A_OFF    0
#define B_OFF    18432
#define STAGE_SZ 36864

__global__ void __launch_bounds__(256, 1) k_mma(const int*   __restrict__ cat_ids,
                                                const float* __restrict__ b3,
                                                float*       __restrict__ out)
{
    extern __shared__ __align__(16) char smem[];

    const int pid = blockIdx.x;
    const int jq  = blockIdx.y;
    if (pid >= g_npairs) return;

    const int2 pr = g_pairs[pid];
    const int b0  = pr.x;
    const int b1  = (pr.y < 0) ? pr.x : pr.y;
    const bool has_b1 = (pr.y >= 0);
    const int e   = cat_ids[b0];

    const int tid  = threadIdx.x;
    const int wid  = tid >> 5;
    const int lane = tid & 31;
    const int wm   = wid & 3;    // 4 m-strips of 32
    const int wn   = wid >> 2;   // 2 n-strips of 64

    const __half* yh = g_yh;
    const __half* wh = g_w3h + ((size_t)e * H_ + jq * 128) * H_;

    const uint32_t sb = smem_u32(smem);

    // per-lane ldmatrix offsets
    const uint32_t arow  = (lane & 7) | (((lane >> 3) & 1) << 3);
    const uint32_t aoff  = (wm * 32 + arow) * KPB + (lane >> 4) * 16;
    const uint32_t nrow  = (lane & 7) | (((lane >> 4) & 1) << 3);
    const uint32_t boff  = (wn * 64 + nrow) * KPB + ((lane >> 3) & 1) * 16;

    #define LOADCHUNK(kc, p) do {                                               \
        char* _d = smem + (p) * STAGE_SZ;                                       \
        _Pragma("unroll")                                                       \
        for (int _l = 0; _l < 4; _l++) {                                        \
            int _i = tid + _l * 256;                                            \
            int _row = _i >> 3, _k8 = _i & 7;                                   \
            uint32_t _off = _row * KPB + _k8 * 16;                              \
            size_t _g = ((size_t)(((_row < 64) ? b0 : b1) * 64 + (_row & 63))) * 512 \
                        + (kc) * 64 + _k8 * 8;                                  \
            cp16(_d + A_OFF + _off, yh + _g);                                   \
        }                                                                       \
        _Pragma("unroll")                                                       \
        for (int _l = 0; _l < 4; _l++) {                                        \
            int _i = tid + _l * 256;                                            \
            int _n = _i >> 3, _k8 = _i & 7;                                     \
            uint32_t _off = _n * KPB + _k8 * 16;                                \
            size_t _g = (size_t)_n * 512 + (kc) * 64 + _k8 * 8;                 \
            cp16(_d + B_OFF + _off, wh + _g);                                   \
        }                                                                       \
        cp_commit();                                                            \
    } while (0)

    float acc[2][8][4];
    #pragma unroll
    for (int mt = 0; mt < 2; mt++)
        #pragma unroll
        for (int nt = 0; nt < 8; nt++)
            #pragma unroll
            for (int q = 0; q < 4; q++) acc[mt][nt][q] = 0.0f;

    LOADCHUNK(0, 0);

    for (int kc = 0; kc < 8; kc++) {
        cp_wait0();
        __syncthreads();
        if (kc < 7) LOADCHUNK(kc + 1, (kc + 1) & 1);

        const uint32_t stg = sb + (kc & 1) * STAGE_SZ;
        #pragma unroll
        for (int ks = 0; ks < 4; ks++) {
            const uint32_t kb = ks * 32;  // 16 fp16 = 32 bytes per k-step
            uint32_t ah[2][4], bh[4][4];

            #pragma unroll
            for (int mt = 0; mt < 2; mt++)
                ldsm4(ah[mt], stg + aoff + mt * (16 * KPB) + kb + A_OFF);
            #pragma unroll
            for (int nt = 0; nt < 4; nt++)
                ldsm4(bh[nt], stg + boff + nt * (16 * KPB) + kb + B_OFF);

            // single pass: y * W  (16 distinct accumulators)
            #pragma unroll
            for (int nt = 0; nt < 4; nt++)
                #pragma unroll
                for (int mt = 0; mt < 2; mt++) {
                    mma16816(acc[mt][2 * nt],     ah[mt], bh[nt][0], bh[nt][1]);
                    mma16816(acc[mt][2 * nt + 1], ah[mt], bh[nt][2], bh[nt][3]);
                }
        }
    }

    // epilogue: c frag (m16n8): thread t -> rows {t/4, t/4+8}, cols {2(t%4), +1}
    {
        const int rgrp = lane >> 2;
        const int cgrp = 2 * (lane & 3);
        const float* b3e = b3 + e * H_;
        #pragma unroll
        for (int mt = 0; mt < 2; mt++) {
            const int r0 = wm * 32 + mt * 16 + rgrp;       // 0..127
            #pragma unroll
            for (int half = 0; half < 2; half++) {
                const int r = r0 + half * 8;
                const int bsel = (r < 64) ? b0 : b1;
                if (r >= 64 && !has_b1) continue;
                float* outr = out + ((size_t)bsel * 64 + (r & 63)) * 512;
                #pragma unroll
                for (int nt = 0; nt < 8; nt++) {
                    const int col = jq * 128 + wn * 64 + nt * 8 + cgrp;
                    float2 o;
                    o.x = acc[mt][nt][half * 2 + 0] + b3e[col];
                    o.y = acc[mt][nt][half * 2 + 1] + b3e[col + 1];
                    *(float2*)&outr[col] = o;
                }
            }
        }
    }
    #undef LOADCHUNK
}

// ---------------------------------------------------------------------------
extern "C" void kernel_launch(void* const* d_in, const int* in_sizes, int n_in,
                              void* d_out, int out_size)
{
    const float* actions = (const float*)d_in[0];
    const float* ts      = (const float*)d_in[1];
    const int*   cat     = (const int*)  d_in[2];
    const float* W1      = (const float*)d_in[3];
    const float* b1      = (const float*)d_in[4];
    const float* W2      = (const float*)d_in[5];
    const float* b2      = (const float*)d_in[6];
    const float* W3      = (const float*)d_in[7];
    const float* b3      = (const float*)d_in[8];
    float*       out     = (float*)d_out;

    const int smem_prep = (256 * 34 + 2 * 32 * 256) * 4;   // ~100 KB
    const int smem_y    = (32 * 256 + 64 * 32) * 4;        //  40 KB
    const int smem_mma  = 2 * STAGE_SZ;                    //  72 KB

    cudaFuncSetAttribute(k_prep, cudaFuncAttributeMaxDynamicSharedMemorySize, smem_prep);
    cudaFuncSetAttribute(k_y,    cudaFuncAttributeMaxDynamicSharedMemorySize, smem_y);
    cudaFuncSetAttribute(k_mma,  cudaFuncAttributeMaxDynamicSharedMemorySize, smem_mma);

    k_prep<<<769, 256, smem_prep>>>(ts, cat, W1, b1, W2, b2, W3);
    k_red <<<384, 512>>>();
    k_y   <<<dim3(B_, 2), 512, smem_y>>>(actions, cat);
    k_mma <<<dim3(272, 4), 256, smem_mma>>>(cat, b3, out);
}

// round 16
// speedup vs baseline: 1.9558x; 1.3442x over previous
#include <cuda_runtime.h>
#include <cuda_bf16.h>
#include <cuda_fp16.h>
#include <stdint.h>
#include <math.h>

#define B_ 512
#define T_ 64
#define A_ 32
#define H_ 512
#define E_ 32

typedef unsigned long long u64;

// scratch (device globals; allocation forbidden)
__device__ float g_M1[E_ * 64 * H_];          // split-K partials of W1@W2_top
__device__ float g_M1r[E_ * 32 * H_];         // reduced M1 (E,32,512)
__device__ float g_V2[2][B_ * H_];            // split-K partials of bias
__device__ float g_V[B_ * H_];                // reduced bias (B,512)
__device__ __half g_yh[B_ * T_ * H_];         // layer-1 output fp16 [b*64+t][k]
__device__ __half g_w3h[(size_t)E_ * H_ * H_]; // W3^T fp16 [e][n][k]
__device__ int2 g_pairs[272];
__device__ int  g_npairs;

#define DEV __device__ __forceinline__

DEV u64 pack2(float x) { u64 r; asm("mov.b64 %0, {%1, %1};" : "=l"(r) : "f"(x)); return r; }
DEV void fma2(u64 &d, u64 a, u64 b) { asm("fma.rn.f32x2 %0, %1, %2, %0;" : "+l"(d) : "l"(a), "l"(b)); }
DEV float2 unpk(u64 a) { float2 f; asm("mov.b64 {%0, %1}, %2;" : "=f"(f.x), "=f"(f.y) : "l"(a)); return f; }

DEV void cp16(void* dst, const void* src) {
    unsigned d = (unsigned)__cvta_generic_to_shared(dst);
    asm volatile("cp.async.cg.shared.global [%0], [%1], 16;" :: "r"(d), "l"(src));
}
DEV void cp_commit() { asm volatile("cp.async.commit_group;"); }
DEV void cp_wait0()  { asm volatile("cp.async.wait_group 0;"); }

union F4 { float4 v; float f[4]; u64 u[2]; };

DEV float swishf(float z) { return z / (1.0f + expf(-z)); }

DEV uint32_t smem_u32(const void* p) {
    uint32_t a;
    asm("{ .reg .u64 t; cvta.to.shared.u64 t, %1; cvt.u32.u64 %0, t; }" : "=r"(a) : "l"(p));
    return a;
}

DEV void ldsm4(uint32_t* r, uint32_t a) {
    asm volatile("ldmatrix.sync.aligned.m8n8.x4.shared.b16 {%0,%1,%2,%3}, [%4];"
                 : "=r"(r[0]), "=r"(r[1]), "=r"(r[2]), "=r"(r[3]) : "r"(a));
}
DEV void mma16816(float* c, const uint32_t* a, uint32_t b0, uint32_t b1) {
    asm volatile("mma.sync.aligned.m16n8k16.row.col.f32.f16.f16.f32 "
                 "{%0,%1,%2,%3}, {%4,%5,%6,%7}, {%8,%9}, {%0,%1,%2,%3};"
                 : "+f"(c[0]), "+f"(c[1]), "+f"(c[2]), "+f"(c[3])
                 : "r"(a[0]), "r"(a[1]), "r"(a[2]), "r"(a[3]), "r"(b0), "r"(b1));
}

// ---------------------------------------------------------------------------
// k_prep: 769 CTAs x 256 threads (R15 structure; pair list now PARALLEL)
//   [0,128)    M1 split-K partial      (e = cid>>2, j-half, k-half)
//   [128,256)  V split-K partial
//   [256,768)  W3 -> transposed fp16 (4 64x64 tiles per CTA)
//   768        pair list (counting sort, ~2 us instead of serial scan)
// ---------------------------------------------------------------------------
__global__ void __launch_bounds__(256) k_prep(const float* __restrict__ ts,
                                              const int*   __restrict__ cat,
                                              const float* __restrict__ W1,
                                              const float* __restrict__ b1,
                                              const float* __restrict__ W2,
                                              const float* __restrict__ b2,
                                              const float* __restrict__ W3)
{
    extern __shared__ float sm[];
    const int cid = blockIdx.x;
    const int tid = threadIdx.x;

    if (cid < 128) {
        // ---------------- M1 partial ----------------
        const int e  = cid >> 2;
        const int j0 = ((cid >> 1) & 1) * 256;
        const int kz = cid & 1;
        const int j  = j0 + tid;

        float* w1t = sm;                 // [256 hh][34]
        float* wt  = sm + 256 * 34;      // 2 x [32][256]

        const float* W1e = W1 + e * (A_ * H_);
        const float* W2h = W2 + e * (2 * H_ * H_) + kz * 256 * H_ + j0;

        #pragma unroll
        for (int l = 0; l < 8; l++) {
            int i = tid + l * 256;
            int r = i >> 6, c4 = (i & 63) << 2;
            cp16(wt + r * 256 + c4, W2h + r * H_ + c4);
        }
        cp_commit();

        for (int i = tid; i < 32 * 256; i += 256) {
            int a = i >> 8, hh = i & 255;
            w1t[hh * 34 + a] = W1e[a * H_ + kz * 256 + hh];
        }

        u64 acc[16];
        #pragma unroll
        for (int p = 0; p < 16; p++) acc[p] = 0ULL;

        for (int kt = 0; kt < 8; kt++) {
            cp_wait0();
            __syncthreads();
            if (kt < 7) {
                const float* src = W2h + (kt + 1) * 32 * H_;
                float* dst = wt + ((kt + 1) & 1) * (32 * 256);
                #pragma unroll
                for (int l = 0; l < 8; l++) {
                    int i = tid + l * 256;
                    int r = i >> 6, c4 = (i & 63) << 2;
                    cp16(dst + r * 256 + c4, src + r * H_ + c4);
                }
                cp_commit();
            }
            const float* cur = wt + (kt & 1) * (32 * 256);
            #pragma unroll 2
            for (int hl = 0; hl < 32; hl++) {
                const int hh = kt * 32 + hl;
                u64 wd = pack2(cur[hl * 256 + tid]);
                #pragma unroll
                for (int p = 0; p < 16; p++)
                    fma2(acc[p], *(const u64*)&w1t[hh * 34 + 2 * p], wd);
            }
        }
        float* M1e = g_M1 + e * (64 * H_) + kz * 32 * H_;
        #pragma unroll
        for (int p = 0; p < 16; p++) {
            float2 f = unpk(acc[p]);
            M1e[(2 * p) * H_ + j]     = f.x;
            M1e[(2 * p + 1) * H_ + j] = f.y;
        }
    } else if (cid < 256) {
        // ---------------- V partial ----------------
        const int vc = cid - 128;
        const int e  = vc >> 2;
        const int j0 = ((vc >> 1) & 1) * 256;
        const int kz = vc & 1;
        const int j  = j0 + tid;

        float* trig = sm;                         // [256 k][16 b]
        float* wt   = sm + 256 * 16;              // 2 x [32][256]
        int*   list = (int*)(sm + 256 * 16 + 2 * 32 * 256);
        int*   pn   = list + B_;

        if (tid == 0) *pn = 0;
        __syncthreads();
        for (int b = tid; b < B_; b += 256)
            if (cat[b] == e) { int p = atomicAdd(pn, 1); list[p] = b; }

        int nzl = (b1[e * H_ + kz * 256 + tid] != 0.0f);
        const int nz = __syncthreads_or(nzl);
        const int nb = *pn;

        const float* W2e = W2 + e * (2 * H_ * H_);
        float cb = (kz == 0) ? b2[e * H_ + j] : 0.0f;
        if (nz) {
            #pragma unroll 8
            for (int h = 0; h < 256; h++)
                cb += b1[e * H_ + kz * 256 + h] * W2e[(kz * 256 + h) * H_ + j];
        }

        const float L = 9.210340371976184f / 256.0f;
        const float* W2bot = W2e + H_ * H_ + kz * 256 * H_ + j0;

        for (int bg = 0; bg * 16 < nb; bg++) {
            const int m = min(16, nb - bg * 16);
            __syncthreads();
            for (int i = tid; i < 16 * 256; i += 256) {
                int k = i >> 4, q = i & 15;
                float t = (q < m) ? ts[list[bg * 16 + q]] : 0.0f;
                float ang = t * expf(-L * (float)k);
                trig[k * 16 + q] = kz ? cosf(ang) : sinf(ang);
            }
            #pragma unroll
            for (int l = 0; l < 8; l++) {
                int i = tid + l * 256;
                int r = i >> 6, c4 = (i & 63) << 2;
                cp16(wt + r * 256 + c4, W2bot + r * H_ + c4);
            }
            cp_commit();

            u64 acc[8];
            #pragma unroll
            for (int q = 0; q < 8; q++) acc[q] = 0ULL;

            for (int kt = 0; kt < 8; kt++) {
                cp_wait0();
                __syncthreads();
                if (kt < 7) {
                    const float* src = W2bot + (kt + 1) * 32 * H_;
                    float* dst = wt + ((kt + 1) & 1) * (32 * 256);
                    #pragma unroll
                    for (int l = 0; l < 8; l++) {
                        int i = tid + l * 256;
                        int r = i >> 6, c4 = (i & 63) << 2;
                        cp16(dst + r * 256 + c4, src + r * H_ + c4);
                    }
                    cp_commit();
                }
                const float* cur = wt + (kt & 1) * (32 * 256);
                #pragma unroll 2
                for (int kk = 0; kk < 32; kk++) {
                    const int k = kt * 32 + kk;
                    u64 wd = pack2(cur[kk * 256 + tid]);
                    #pragma unroll
                    for (int q = 0; q < 8; q++)
                        fma2(acc[q], *(const u64*)&trig[k * 16 + 2 * q], wd);
                }
            }
            #pragma unroll
            for (int q = 0; q < 8; q++) {
                float2 f = unpk(acc[q]);
                if (2 * q < m)     g_V2[kz][list[bg * 16 + 2 * q] * H_ + j]     = f.x + cb;
                if (2 * q + 1 < m) g_V2[kz][list[bg * 16 + 2 * q + 1] * H_ + j] = f.y + cb;
            }
        }
    } else if (cid < 768) {
        // -------- W3 transpose + fp16 round (4 tiles) --------
        float (*tile)[65] = (float(*)[65])sm;     // [64][65]
        const int wc = cid - 256;                 // 0..511
        const int e  = wc >> 4;
        const int tbase = (wc & 15) * 4;
        #pragma unroll
        for (int ti = 0; ti < 4; ti++) {
            const int t  = tbase + ti;            // 0..63
            const int kb = (t >> 3) * 64;
            const int nb = (t & 7) * 64;
            const float* src = W3 + ((size_t)e * H_ + kb) * H_ + nb;
            __syncthreads();
            #pragma unroll
            for (int l = 0; l < 16; l++) {
                int i = tid + l * 256;
                int r = i >> 6, c = i & 63;
                tile[r][c] = src[(size_t)r * H_ + c];
            }
            __syncthreads();
            #pragma unroll
            for (int l = 0; l < 16; l++) {
                int i = tid + l * 256;
                int r = i >> 6, c = i & 63;        // r = n-local, c = k-local
                size_t o = ((size_t)e * H_ + nb + r) * H_ + kb + c;
                g_w3h[o] = __float2half_rn(tile[c][r]);
            }
        }
    } else {
        // ------- pair list: parallel counting sort (no serial scan) -------
        int* cnt  = (int*)sm;            // [32]
        int* base = (int*)sm + 32;       // [32]
        int* cur  = (int*)sm + 64;       // [32]
        int* slot = (int*)sm + 96;       // [512]

        if (tid == 0) g_npairs = 0;
        if (tid < 32) cnt[tid] = 0;
        __syncthreads();

        // phase 1: count per expert (2 coalesced passes)
        for (int b = tid; b < B_; b += 256)
            atomicAdd(&cnt[cat[b]], 1);
        __syncthreads();

        // phase 2: serial 32-element prefix (1 thread, trivial)
        if (tid == 0) {
            int off = 0;
            for (int e = 0; e < E_; e++) { base[e] = off; cur[e] = off; off += cnt[e]; }
        }
        __syncthreads();

        // phase 3: scatter batches by expert rank
        for (int b = tid; b < B_; b += 256) {
            int e = cat[b];
            int p = atomicAdd(&cur[e], 1);
            slot[p] = b;
        }
        __syncthreads();

        // phase 4: emit pairs (any same-expert pairing is output-equivalent)
        if (tid < 32) {
            const int e = tid;
            const int n = cnt[e], bs = base[e];
            const int npe = (n + 1) >> 1;
            int pbase = (npe > 0) ? atomicAdd(&g_npairs, npe) : 0;
            for (int i = 0; i < npe; i++) {
                int x = slot[bs + 2 * i];
                int y = (2 * i + 1 < n) ? slot[bs + 2 * i + 1] : -1;
                g_pairs[pbase + i] = make_int2(x, y);
            }
        }
    }
}

// ---------------------------------------------------------------------------
// k_red: fold split-K partials (R8 version, measured 5.4 us)
// ---------------------------------------------------------------------------
__global__ void __launch_bounds__(512) k_red()
{
    const int i = blockIdx.x * 512 + threadIdx.x;
    const float4* m1 = (const float4*)g_M1;
    if (i < 131072) {
        int e = i >> 12, r = i & 4095;
        F4 a, b;
        a.v = m1[e * 8192 + r];
        b.v = m1[e * 8192 + 4096 + r];
        #pragma unroll
        for (int q = 0; q < 4; q++) a.f[q] += b.f[q];
        ((float4*)g_M1r)[i] = a.v;
    } else {
        int r = i - 131072;
        F4 a, b;
        a.v = ((const float4*)g_V2[0])[r];
        b.v = ((const float4*)g_V2[1])[r];
        #pragma unroll
        for (int q = 0; q < 4; q++) a.f[q] += b.f[q];
        ((float4*)g_V)[r] = a.v;
    }
}

// ---------------------------------------------------------------------------
// k_y helpers (SIMT layer-1)
// ---------------------------------------------------------------------------
template <int NK4>
DEV void mma4(const float* __restrict__ wb, const float* __restrict__ yrow,
              int ystride, u64 (&acc)[4][4], int t0, int jb)
{
    #pragma unroll
    for (int k4 = 0; k4 < NK4; k4++) {
        F4 yv[4];
        #pragma unroll
        for (int r = 0; r < 4; r++)
            yv[r].v = *(const float4*)&yrow[(t0 + r) * ystride + k4 * 4];
        #pragma unroll
        for (int kk = 0; kk < 4; kk++) {
            F4 w0, w1;
            w0.v = *(const float4*)&wb[(k4 * 4 + kk) * 256 + jb];
            w1.v = *(const float4*)&wb[(k4 * 4 + kk) * 256 + jb + 128];
            #pragma unroll
            for (int r = 0; r < 4; r++) {
                u64 yd = pack2(yv[r].f[kk]);
                fma2(acc[r][0], yd, w0.u[0]);
                fma2(acc[r][1], yd, w0.u[1]);
                fma2(acc[r][2], yd, w1.u[0]);
                fma2(acc[r][3], yd, w1.u[1]);
            }
        }
    }
}

// ---------------------------------------------------------------------------
// k_y: y = swish(actions @ M1r + v), rounded once to fp16.  grid (B,2) x 512
// ---------------------------------------------------------------------------
__global__ void __launch_bounds__(512) k_y(const float* __restrict__ actions,
                                           const int*   __restrict__ cat_ids)
{
    extern __shared__ float sm[];
    float* m1  = sm;              // [32][256]
    float* act = sm + 32 * 256;   // [64][32]

    const int tid = threadIdx.x;
    const int b   = blockIdx.x;
    const int jh  = blockIdx.y;
    const int e   = cat_ids[b];
    const int t0  = (tid >> 5) * 4;
    const int jb  = (tid & 31) * 4;

    const float* M1e  = g_M1r + e * (32 * H_) + jh * 256;
    const float* actb = actions + b * (T_ * A_);

    #pragma unroll
    for (int l = 0; l < 4; l++) {
        int i = tid + l * 512;
        int r = i >> 6, c4 = (i & 63) << 2;
        cp16(m1 + r * 256 + c4, M1e + (size_t)r * H_ + c4);
    }
    cp16(act + tid * 4, actb + tid * 4);
    cp_commit();
    cp_wait0();
    __syncthreads();

    u64 acc[4][4];
    #pragma unroll
    for (int r = 0; r < 4; r++)
        #pragma unroll
        for (int c = 0; c < 4; c++) acc[r][c] = 0ULL;

    mma4<4>(m1,            act,      32, acc, t0, jb);
    mma4<4>(m1 + 16 * 256, act + 16, 32, acc, t0, jb);

    const float* vp = g_V + b * H_ + jh * 256;
    F4 v0, v1;
    v0.v = *(const float4*)&vp[jb];
    v1.v = *(const float4*)&vp[jb + 128];

    #pragma unroll
    for (int r = 0; r < 4; r++) {
        float y[8];
        float2 a0 = unpk(acc[r][0]), a1 = unpk(acc[r][1]);
        float2 a2 = unpk(acc[r][2]), a3 = unpk(acc[r][3]);
        y[0] = swishf(a0.x + v0.f[0]); y[1] = swishf(a0.y + v0.f[1]);
        y[2] = swishf(a1.x + v0.f[2]); y[3] = swishf(a1.y + v0.f[3]);
        y[4] = swishf(a2.x + v1.f[0]); y[5] = swishf(a2.y + v1.f[1]);
        y[6] = swishf(a3.x + v1.f[2]); y[7] = swishf(a3.y + v1.f[3]);

        __half hi[8];
        #pragma unroll
        for (int q = 0; q < 8; q++)
            hi[q] = __float2half_rn(y[q]);
        size_t base = ((size_t)b * 64 + t0 + r) * 512 + jh * 256;
        *(uint2*)&g_yh[base + jb]       = *(uint2*)&hi[0];
        *(uint2*)&g_yh[base + jb + 128] = *(uint2*)&hi[4];
    }
}

// ---------------------------------------------------------------------------
// k_mma: layer 2 on warp-level HMMA, PURE fp16 (single pass), fp32 accum.
//  (EXACT R15 version — measured 79.7 us.)
//  grid (272, 4) x 256 threads.  CTA (pid, jq): M=128 pair rows, N=128
//  quarter; warp grid 4m x 2n -> warp tile 32x64, 16 frag accumulators.
//  K=512 in 8 chunks of 64, cp.async 2-stage double buffer (72 KB smem).
// ---------------------------------------------------------------------------
#define KPB  144
#define A_OFF    0
#define B_OFF    18432
#define STAGE_SZ 36864

__global__ void __launch_bounds__(256, 1) k_mma(const int*   __restrict__ cat_ids,
                                                const float* __restrict__ b3,
                                                float*       __restrict__ out)
{
    extern __shared__ __align__(16) char smem[];

    const int pid = blockIdx.x;
    const int jq  = blockIdx.y;
    if (pid >= g_npairs) return;

    const int2 pr = g_pairs[pid];
    const int b0  = pr.x;
    const int b1  = (pr.y < 0) ? pr.x : pr.y;
    const bool has_b1 = (pr.y >= 0);
    const int e   = cat_ids[b0];

    const int tid  = threadIdx.x;
    const int wid  = tid >> 5;
    const int lane = tid & 31;
    const int wm   = wid & 3;    // 4 m-strips of 32
    const int wn   = wid >> 2;   // 2 n-strips of 64

    const __half* yh = g_yh;
    const __half* wh = g_w3h + ((size_t)e * H_ + jq * 128) * H_;

    const uint32_t sb = smem_u32(smem);

    // per-lane ldmatrix offsets
    const uint32_t arow  = (lane & 7) | (((lane >> 3) & 1) << 3);
    const uint32_t aoff  = (wm * 32 + arow) * KPB + (lane >> 4) * 16;
    const uint32_t nrow  = (lane & 7) | (((lane >> 4) & 1) << 3);
    const uint32_t boff  = (wn * 64 + nrow) * KPB + ((lane >> 3) & 1) * 16;

    #define LOADCHUNK(kc, p) do {                                               \
        char* _d = smem + (p) * STAGE_SZ;                                       \
        _Pragma("unroll")                                                       \
        for (int _l = 0; _l < 4; _l++) {                                        \
            int _i = tid + _l * 256;                                            \
            int _row = _i >> 3, _k8 = _i & 7;                                   \
            uint32_t _off = _row * KPB + _k8 * 16;                              \
            size_t _g = ((size_t)(((_row < 64) ? b0 : b1) * 64 + (_row & 63))) * 512 \
                        + (kc) * 64 + _k8 * 8;                                  \
            cp16(_d + A_OFF + _off, yh + _g);                                   \
        }                                                                       \
        _Pragma("unroll")                                                       \
        for (int _l = 0; _l < 4; _l++) {                                        \
            int _i = tid + _l * 256;                                            \
            int _n = _i >> 3, _k8 = _i & 7;                                     \
            uint32_t _off = _n * KPB + _k8 * 16;                                \
            size_t _g = (size_t)_n * 512 + (kc) * 64 + _k8 * 8;                 \
            cp16(_d + B_OFF + _off, wh + _g);                                   \
        }                                                                       \
        cp_commit();                                                            \
    } while (0)

    float acc[2][8][4];
    #pragma unroll
    for (int mt = 0; mt < 2; mt++)
        #pragma unroll
        for (int nt = 0; nt < 8; nt++)
            #pragma unroll
            for (int q = 0; q < 4; q++) acc[mt][nt][q] = 0.0f;

    LOADCHUNK(0, 0);

    for (int kc = 0; kc < 8; kc++) {
        cp_wait0();
        __syncthreads();
        if (kc < 7) LOADCHUNK(kc + 1, (kc + 1) & 1);

        const uint32_t stg = sb + (kc & 1) * STAGE_SZ;
        #pragma unroll
        for (int ks = 0; ks < 4; ks++) {
            const uint32_t kb = ks * 32;  // 16 fp16 = 32 bytes per k-step
            uint32_t ah[2][4], bh[4][4];

            #pragma unroll
            for (int mt = 0; mt < 2; mt++)
                ldsm4(ah[mt], stg + aoff + mt * (16 * KPB) + kb + A_OFF);
            #pragma unroll
            for (int nt = 0; nt < 4; nt++)
                ldsm4(bh[nt], stg + boff + nt * (16 * KPB) + kb + B_OFF);

            // single pass: y * W  (16 distinct accumulators)
            #pragma unroll
            for (int nt = 0; nt < 4; nt++)
                #pragma unroll
                for (int mt = 0; mt < 2; mt++) {
                    mma16816(acc[mt][2 * nt],     ah[mt], bh[nt][0], bh[nt][1]);
                    mma16816(acc[mt][2 * nt + 1], ah[mt], bh[nt][2], bh[nt][3]);
                }
        }
    }

    // epilogue: c frag (m16n8): thread t -> rows {t/4, t/4+8}, cols {2(t%4), +1}
    {
        const int rgrp = lane >> 2;
        const int cgrp = 2 * (lane & 3);
        const float* b3e = b3 + e * H_;
        #pragma unroll
        for (int mt = 0; mt < 2; mt++) {
            const int r0 = wm * 32 + mt * 16 + rgrp;       // 0..127
            #pragma unroll
            for (int half = 0; half < 2; half++) {
                const int r = r0 + half * 8;
                const int bsel = (r < 64) ? b0 : b1;
                if (r >= 64 && !has_b1) continue;
                float* outr = out + ((size_t)bsel * 64 + (r & 63)) * 512;
                #pragma unroll
                for (int nt = 0; nt < 8; nt++) {
                    const int col = jq * 128 + wn * 64 + nt * 8 + cgrp;
                    float2 o;
                    o.x = acc[mt][nt][half * 2 + 0] + b3e[col];
                    o.y = acc[mt][nt][half * 2 + 1] + b3e[col + 1];
                    *(float2*)&outr[col] = o;
                }
            }
        }
    }
    #undef LOADCHUNK
}

// ---------------------------------------------------------------------------
extern "C" void kernel_launch(void* const* d_in, const int* in_sizes, int n_in,
                              void* d_out, int out_size)
{
    const float* actions = (const float*)d_in[0];
    const float* ts      = (const float*)d_in[1];
    const int*   cat     = (const int*)  d_in[2];
    const float* W1      = (const float*)d_in[3];
    const float* b1      = (const float*)d_in[4];
    const float* W2      = (const float*)d_in[5];
    const float* b2      = (const float*)d_in[6];
    const float* W3      = (const float*)d_in[7];
    const float* b3      = (const float*)d_in[8];
    float*       out     = (float*)d_out;

    const int smem_prep = (256 * 34 + 2 * 32 * 256) * 4;   // ~100 KB
    const int smem_y    = (32 * 256 + 64 * 32) * 4;        //  40 KB
    const int smem_mma  = 2 * STAGE_SZ;                    //  72 KB

    cudaFuncSetAttribute(k_prep, cudaFuncAttributeMaxDynamicSharedMemorySize, smem_prep);
    cudaFuncSetAttribute(k_y,    cudaFuncAttributeMaxDynamicSharedMemorySize, smem_y);
    cudaFuncSetAttribute(k_mma,  cudaFuncAttributeMaxDynamicSharedMemorySize, smem_mma);

    k_prep<<<769, 256, smem_prep>>>(ts, cat, W1, b1, W2, b2, W3);
    k_red <<<384, 512>>>();
    k_y   <<<dim3(B_, 2), 512, smem_y>>>(actions, cat);
    k_mma <<<dim3(272, 4), 256, smem_mma>>>(cat, b3, out);
}

// round 17
// speedup vs baseline: 1.9829x; 1.0138x over previous
#include <cuda_runtime.h>
#include <cuda_bf16.h>
#include <cuda_fp16.h>
#include <stdint.h>
#include <math.h>

#define B_ 512
#define T_ 64
#define A_ 32
#define H_ 512
#define E_ 32

typedef unsigned long long u64;

// scratch (device globals; allocation forbidden)
__device__ float g_M1[E_ * 64 * H_];          // split-K partials of W1@W2_top
__device__ float g_M1r[E_ * 32 * H_];         // reduced M1 (E,32,512)
__device__ float g_V2[2][B_ * H_];            // split-K partials of bias
__device__ float g_V[B_ * H_];                // reduced bias (B,512)
__device__ __half g_yh[B_ * T_ * H_];         // layer-1 output fp16 [b*64+t][k]
__device__ __half g_w3h[(size_t)E_ * H_ * H_]; // W3^T fp16 [e][n][k]
__device__ int2 g_pairs[272];
__device__ int  g_npairs;

#define DEV __device__ __forceinline__

DEV u64 pack2(float x) { u64 r; asm("mov.b64 %0, {%1, %1};" : "=l"(r) : "f"(x)); return r; }
DEV void fma2(u64 &d, u64 a, u64 b) { asm("fma.rn.f32x2 %0, %1, %2, %0;" : "+l"(d) : "l"(a), "l"(b)); }
DEV float2 unpk(u64 a) { float2 f; asm("mov.b64 {%0, %1}, %2;" : "=f"(f.x), "=f"(f.y) : "l"(a)); return f; }

DEV void cp16(void* dst, const void* src) {
    unsigned d = (unsigned)__cvta_generic_to_shared(dst);
    asm volatile("cp.async.cg.shared.global [%0], [%1], 16;" :: "r"(d), "l"(src));
}
DEV void cp_commit() { asm volatile("cp.async.commit_group;"); }
DEV void cp_wait0()  { asm volatile("cp.async.wait_group 0;"); }
DEV void cp_wait1()  { asm volatile("cp.async.wait_group 1;"); }
DEV void cp_wait2()  { asm volatile("cp.async.wait_group 2;"); }

union F4 { float4 v; float f[4]; u64 u[2]; };

DEV float swishf(float z) { return z / (1.0f + expf(-z)); }

DEV uint32_t smem_u32(const void* p) {
    uint32_t a;
    asm("{ .reg .u64 t; cvta.to.shared.u64 t, %1; cvt.u32.u64 %0, t; }" : "=r"(a) : "l"(p));
    return a;
}

DEV void ldsm4(uint32_t* r, uint32_t a) {
    asm volatile("ldmatrix.sync.aligned.m8n8.x4.shared.b16 {%0,%1,%2,%3}, [%4];"
                 : "=r"(r[0]), "=r"(r[1]), "=r"(r[2]), "=r"(r[3]) : "r"(a));
}
DEV void mma16816(float* c, const uint32_t* a, uint32_t b0, uint32_t b1) {
    asm volatile("mma.sync.aligned.m16n8k16.row.col.f32.f16.f16.f32 "
                 "{%0,%1,%2,%3}, {%4,%5,%6,%7}, {%8,%9}, {%0,%1,%2,%3};"
                 : "+f"(c[0]), "+f"(c[1]), "+f"(c[2]), "+f"(c[3])
                 : "r"(a[0]), "r"(a[1]), "r"(a[2]), "r"(a[3]), "r"(b0), "r"(b1));
}

// ---------------------------------------------------------------------------
// k_prep: 769 CTAs x 256 threads (EXACT R16 version — measured best)
//   [0,128)    M1 split-K partial      (e = cid>>2, j-half, k-half)
//   [128,256)  V split-K partial
//   [256,768)  W3 -> transposed fp16 (4 64x64 tiles per CTA)
//   768        pair list (parallel counting sort)
// ---------------------------------------------------------------------------
__global__ void __launch_bounds__(256) k_prep(const float* __restrict__ ts,
                                              const int*   __restrict__ cat,
                                              const float* __restrict__ W1,
                                              const float* __restrict__ b1,
                                              const float* __restrict__ W2,
                                              const float* __restrict__ b2,
                                              const float* __restrict__ W3)
{
    extern __shared__ float sm[];
    const int cid = blockIdx.x;
    const int tid = threadIdx.x;

    if (cid < 128) {
        // ---------------- M1 partial ----------------
        const int e  = cid >> 2;
        const int j0 = ((cid >> 1) & 1) * 256;
        const int kz = cid & 1;
        const int j  = j0 + tid;

        float* w1t = sm;                 // [256 hh][34]
        float* wt  = sm + 256 * 34;      // 2 x [32][256]

        const float* W1e = W1 + e * (A_ * H_);
        const float* W2h = W2 + e * (2 * H_ * H_) + kz * 256 * H_ + j0;

        #pragma unroll
        for (int l = 0; l < 8; l++) {
            int i = tid + l * 256;
            int r = i >> 6, c4 = (i & 63) << 2;
            cp16(wt + r * 256 + c4, W2h + r * H_ + c4);
        }
        cp_commit();

        for (int i = tid; i < 32 * 256; i += 256) {
            int a = i >> 8, hh = i & 255;
            w1t[hh * 34 + a] = W1e[a * H_ + kz * 256 + hh];
        }

        u64 acc[16];
        #pragma unroll
        for (int p = 0; p < 16; p++) acc[p] = 0ULL;

        for (int kt = 0; kt < 8; kt++) {
            cp_wait0();
            __syncthreads();
            if (kt < 7) {
                const float* src = W2h + (kt + 1) * 32 * H_;
                float* dst = wt + ((kt + 1) & 1) * (32 * 256);
                #pragma unroll
                for (int l = 0; l < 8; l++) {
                    int i = tid + l * 256;
                    int r = i >> 6, c4 = (i & 63) << 2;
                    cp16(dst + r * 256 + c4, src + r * H_ + c4);
                }
                cp_commit();
            }
            const float* cur = wt + (kt & 1) * (32 * 256);
            #pragma unroll 2
            for (int hl = 0; hl < 32; hl++) {
                const int hh = kt * 32 + hl;
                u64 wd = pack2(cur[hl * 256 + tid]);
                #pragma unroll
                for (int p = 0; p < 16; p++)
                    fma2(acc[p], *(const u64*)&w1t[hh * 34 + 2 * p], wd);
            }
        }
        float* M1e = g_M1 + e * (64 * H_) + kz * 32 * H_;
        #pragma unroll
        for (int p = 0; p < 16; p++) {
            float2 f = unpk(acc[p]);
            M1e[(2 * p) * H_ + j]     = f.x;
            M1e[(2 * p + 1) * H_ + j] = f.y;
        }
    } else if (cid < 256) {
        // ---------------- V partial ----------------
        const int vc = cid - 128;
        const int e  = vc >> 2;
        const int j0 = ((vc >> 1) & 1) * 256;
        const int kz = vc & 1;
        const int j  = j0 + tid;

        float* trig = sm;                         // [256 k][16 b]
        float* wt   = sm + 256 * 16;              // 2 x [32][256]
        int*   list = (int*)(sm + 256 * 16 + 2 * 32 * 256);
        int*   pn   = list + B_;

        if (tid == 0) *pn = 0;
        __syncthreads();
        for (int b = tid; b < B_; b += 256)
            if (cat[b] == e) { int p = atomicAdd(pn, 1); list[p] = b; }

        int nzl = (b1[e * H_ + kz * 256 + tid] != 0.0f);
        const int nz = __syncthreads_or(nzl);
        const int nb = *pn;

        const float* W2e = W2 + e * (2 * H_ * H_);
        float cb = (kz == 0) ? b2[e * H_ + j] : 0.0f;
        if (nz) {
            #pragma unroll 8
            for (int h = 0; h < 256; h++)
                cb += b1[e * H_ + kz * 256 + h] * W2e[(kz * 256 + h) * H_ + j];
        }

        const float L = 9.210340371976184f / 256.0f;
        const float* W2bot = W2e + H_ * H_ + kz * 256 * H_ + j0;

        for (int bg = 0; bg * 16 < nb; bg++) {
            const int m = min(16, nb - bg * 16);
            __syncthreads();
            for (int i = tid; i < 16 * 256; i += 256) {
                int k = i >> 4, q = i & 15;
                float t = (q < m) ? ts[list[bg * 16 + q]] : 0.0f;
                float ang = t * expf(-L * (float)k);
                trig[k * 16 + q] = kz ? cosf(ang) : sinf(ang);
            }
            #pragma unroll
            for (int l = 0; l < 8; l++) {
                int i = tid + l * 256;
                int r = i >> 6, c4 = (i & 63) << 2;
                cp16(wt + r * 256 + c4, W2bot + r * H_ + c4);
            }
            cp_commit();

            u64 acc[8];
            #pragma unroll
            for (int q = 0; q < 8; q++) acc[q] = 0ULL;

            for (int kt = 0; kt < 8; kt++) {
                cp_wait0();
                __syncthreads();
                if (kt < 7) {
                    const float* src = W2bot + (kt + 1) * 32 * H_;
                    float* dst = wt + ((kt + 1) & 1) * (32 * 256);
                    #pragma unroll
                    for (int l = 0; l < 8; l++) {
                        int i = tid + l * 256;
                        int r = i >> 6, c4 = (i & 63) << 2;
                        cp16(dst + r * 256 + c4, src + r * H_ + c4);
                    }
                    cp_commit();
                }
                const float* cur = wt + (kt & 1) * (32 * 256);
                #pragma unroll 2
                for (int kk = 0; kk < 32; kk++) {
                    const int k = kt * 32 + kk;
                    u64 wd = pack2(cur[kk * 256 + tid]);
                    #pragma unroll
                    for (int q = 0; q < 8; q++)
                        fma2(acc[q], *(const u64*)&trig[k * 16 + 2 * q], wd);
                }
            }
            #pragma unroll
            for (int q = 0; q < 8; q++) {
                float2 f = unpk(acc[q]);
                if (2 * q < m)     g_V2[kz][list[bg * 16 + 2 * q] * H_ + j]     = f.x + cb;
                if (2 * q + 1 < m) g_V2[kz][list[bg * 16 + 2 * q + 1] * H_ + j] = f.y + cb;
            }
        }
    } else if (cid < 768) {
        // -------- W3 transpose + fp16 round (4 tiles) --------
        float (*tile)[65] = (float(*)[65])sm;     // [64][65]
        const int wc = cid - 256;                 // 0..511
        const int e  = wc >> 4;
        const int tbase = (wc & 15) * 4;
        #pragma unroll
        for (int ti = 0; ti < 4; ti++) {
            const int t  = tbase + ti;            // 0..63
            const int kb = (t >> 3) * 64;
            const int nb = (t & 7) * 64;
            const float* src = W3 + ((size_t)e * H_ + kb) * H_ + nb;
            __syncthreads();
            #pragma unroll
            for (int l = 0; l < 16; l++) {
                int i = tid + l * 256;
                int r = i >> 6, c = i & 63;
                tile[r][c] = src[(size_t)r * H_ + c];
            }
            __syncthreads();
            #pragma unroll
            for (int l = 0; l < 16; l++) {
                int i = tid + l * 256;
                int r = i >> 6, c = i & 63;        // r = n-local, c = k-local
                size_t o = ((size_t)e * H_ + nb + r) * H_ + kb + c;
                g_w3h[o] = __float2half_rn(tile[c][r]);
            }
        }
    } else {
        // ------- pair list: parallel counting sort -------
        int* cnt  = (int*)sm;            // [32]
        int* base = (int*)sm + 32;       // [32]
        int* cur  = (int*)sm + 64;       // [32]
        int* slot = (int*)sm + 96;       // [512]

        if (tid == 0) g_npairs = 0;
        if (tid < 32) cnt[tid] = 0;
        __syncthreads();

        for (int b = tid; b < B_; b += 256)
            atomicAdd(&cnt[cat[b]], 1);
        __syncthreads();

        if (tid == 0) {
            int off = 0;
            for (int e = 0; e < E_; e++) { base[e] = off; cur[e] = off; off += cnt[e]; }
        }
        __syncthreads();

        for (int b = tid; b < B_; b += 256) {
            int e = cat[b];
            int p = atomicAdd(&cur[e], 1);
            slot[p] = b;
        }
        __syncthreads();

        if (tid < 32) {
            const int e = tid;
            const int n = cnt[e], bs = base[e];
            const int npe = (n + 1) >> 1;
            int pbase = (npe > 0) ? atomicAdd(&g_npairs, npe) : 0;
            for (int i = 0; i < npe; i++) {
                int x = slot[bs + 2 * i];
                int y = (2 * i + 1 < n) ? slot[bs + 2 * i + 1] : -1;
                g_pairs[pbase + i] = make_int2(x, y);
            }
        }
    }
}

// ---------------------------------------------------------------------------
// k_red: fold split-K partials (R8 version, measured 5.4 us)
// ---------------------------------------------------------------------------
__global__ void __launch_bounds__(512) k_red()
{
    const int i = blockIdx.x * 512 + threadIdx.x;
    const float4* m1 = (const float4*)g_M1;
    if (i < 131072) {
        int e = i >> 12, r = i & 4095;
        F4 a, b;
        a.v = m1[e * 8192 + r];
        b.v = m1[e * 8192 + 4096 + r];
        #pragma unroll
        for (int q = 0; q < 4; q++) a.f[q] += b.f[q];
        ((float4*)g_M1r)[i] = a.v;
    } else {
        int r = i - 131072;
        F4 a, b;
        a.v = ((const float4*)g_V2[0])[r];
        b.v = ((const float4*)g_V2[1])[r];
        #pragma unroll
        for (int q = 0; q < 4; q++) a.f[q] += b.f[q];
        ((float4*)g_V)[r] = a.v;
    }
}

// ---------------------------------------------------------------------------
// k_y helpers (SIMT layer-1)
// ---------------------------------------------------------------------------
template <int NK4>
DEV void mma4(const float* __restrict__ wb, const float* __restrict__ yrow,
              int ystride, u64 (&acc)[4][4], int t0, int jb)
{
    #pragma unroll
    for (int k4 = 0; k4 < NK4; k4++) {
        F4 yv[4];
        #pragma unroll
        for (int r = 0; r < 4; r++)
            yv[r].v = *(const float4*)&yrow[(t0 + r) * ystride + k4 * 4];
        #pragma unroll
        for (int kk = 0; kk < 4; kk++) {
            F4 w0, w1;
            w0.v = *(const float4*)&wb[(k4 * 4 + kk) * 256 + jb];
            w1.v = *(const float4*)&wb[(k4 * 4 + kk) * 256 + jb + 128];
            #pragma unroll
            for (int r = 0; r < 4; r++) {
                u64 yd = pack2(yv[r].f[kk]);
                fma2(acc[r][0], yd, w0.u[0]);
                fma2(acc[r][1], yd, w0.u[1]);
                fma2(acc[r][2], yd, w1.u[0]);
                fma2(acc[r][3], yd, w1.u[1]);
            }
        }
    }
}

// ---------------------------------------------------------------------------
// k_y: y = swish(actions @ M1r + v), rounded once to fp16.  grid (B,2) x 512
// ---------------------------------------------------------------------------
__global__ void __launch_bounds__(512) k_y(const float* __restrict__ actions,
                                           const int*   __restrict__ cat_ids)
{
    extern __shared__ float sm[];
    float* m1  = sm;              // [32][256]
    float* act = sm + 32 * 256;   // [64][32]

    const int tid = threadIdx.x;
    const int b   = blockIdx.x;
    const int jh  = blockIdx.y;
    const int e   = cat_ids[b];
    const int t0  = (tid >> 5) * 4;
    const int jb  = (tid & 31) * 4;

    const float* M1e  = g_M1r + e * (32 * H_) + jh * 256;
    const float* actb = actions + b * (T_ * A_);

    #pragma unroll
    for (int l = 0; l < 4; l++) {
        int i = tid + l * 512;
        int r = i >> 6, c4 = (i & 63) << 2;
        cp16(m1 + r * 256 + c4, M1e + (size_t)r * H_ + c4);
    }
    cp16(act + tid * 4, actb + tid * 4);
    cp_commit();
    cp_wait0();
    __syncthreads();

    u64 acc[4][4];
    #pragma unroll
    for (int r = 0; r < 4; r++)
        #pragma unroll
        for (int c = 0; c < 4; c++) acc[r][c] = 0ULL;

    mma4<4>(m1,            act,      32, acc, t0, jb);
    mma4<4>(m1 + 16 * 256, act + 16, 32, acc, t0, jb);

    const float* vp = g_V + b * H_ + jh * 256;
    F4 v0, v1;
    v0.v = *(const float4*)&vp[jb];
    v1.v = *(const float4*)&vp[jb + 128];

    #pragma unroll
    for (int r = 0; r < 4; r++) {
        float y[8];
        float2 a0 = unpk(acc[r][0]), a1 = unpk(acc[r][1]);
        float2 a2 = unpk(acc[r][2]), a3 = unpk(acc[r][3]);
        y[0] = swishf(a0.x + v0.f[0]); y[1] = swishf(a0.y + v0.f[1]);
        y[2] = swishf(a1.x + v0.f[2]); y[3] = swishf(a1.y + v0.f[3]);
        y[4] = swishf(a2.x + v1.f[0]); y[5] = swishf(a2.y + v1.f[1]);
        y[6] = swishf(a3.x + v1.f[2]); y[7] = swishf(a3.y + v1.f[3]);

        __half hi[8];
        #pragma unroll
        for (int q = 0; q < 8; q++)
            hi[q] = __float2half_rn(y[q]);
        size_t base = ((size_t)b * 64 + t0 + r) * 512 + jh * 256;
        *(uint2*)&g_yh[base + jb]       = *(uint2*)&hi[0];
        *(uint2*)&g_yh[base + jb + 128] = *(uint2*)&hi[4];
    }
}

// ---------------------------------------------------------------------------
// k_mma: layer 2 on warp-level HMMA, PURE fp16, fp32 accum.
//  R16 geometry, but FOUR-stage cp.async pipeline (4 x 36 KB = 144 KB):
//  prologue issues chunks 0-2; wait has 2-chunk slack -> cp_wait never
//  blocks in steady state (the chunk-quantization stall the profile showed
//  as all-pipes-idle).
//  grid (272, 4) x 256 threads; warp tile 32x64, 16 frag accumulators.
// ---------------------------------------------------------------------------
#define KPB  144
#define A_OFF    0
#define B_OFF    18432
#define STAGE_SZ 36864

__global__ void __launch_bounds__(256, 1) k_mma(const int*   __restrict__ cat_ids,
                                                const float* __restrict__ b3,
                                                float*       __restrict__ out)
{
    extern __shared__ __align__(16) char smem[];

    const int pid = blockIdx.x;
    const int jq  = blockIdx.y;
    if (pid >= g_npairs) return;

    const int2 pr = g_pairs[pid];
    const int b0  = pr.x;
    const int b1  = (pr.y < 0) ? pr.x : pr.y;
    const bool has_b1 = (pr.y >= 0);
    const int e   = cat_ids[b0];

    const int tid  = threadIdx.x;
    const int wid  = tid >> 5;
    const int lane = tid & 31;
    const int wm   = wid & 3;    // 4 m-strips of 32
    const int wn   = wid >> 2;   // 2 n-strips of 64

    const __half* yh = g_yh;
    const __half* wh = g_w3h + ((size_t)e * H_ + jq * 128) * H_;

    const uint32_t sb = smem_u32(smem);

    // per-lane ldmatrix offsets
    const uint32_t arow  = (lane & 7) | (((lane >> 3) & 1) << 3);
    const uint32_t aoff  = (wm * 32 + arow) * KPB + (lane >> 4) * 16;
    const uint32_t nrow  = (lane & 7) | (((lane >> 4) & 1) << 3);
    const uint32_t boff  = (wn * 64 + nrow) * KPB + ((lane >> 3) & 1) * 16;

    #define LOADCHUNK(kc, p) do {                                               \
        char* _d = smem + (p) * STAGE_SZ;                                       \
        _Pragma("unroll")                                                       \
        for (int _l = 0; _l < 4; _l++) {                                        \
            int _i = tid + _l * 256;                                            \
            int _row = _i >> 3, _k8 = _i & 7;                                   \
            uint32_t _off = _row * KPB + _k8 * 16;                              \
            size_t _g = ((size_t)(((_row < 64) ? b0 : b1) * 64 + (_row & 63))) * 512 \
                        + (kc) * 64 + _k8 * 8;                                  \
            cp16(_d + A_OFF + _off, yh + _g);                                   \
        }                                                                       \
        _Pragma("unroll")                                                       \
        for (int _l = 0; _l < 4; _l++) {                                        \
            int _i = tid + _l * 256;                                            \
            int _n = _i >> 3, _k8 = _i & 7;                                     \
            uint32_t _off = _n * KPB + _k8 * 16;                                \
            size_t _g = (size_t)_n * 512 + (kc) * 64 + _k8 * 8;                 \
            cp16(_d + B_OFF + _off, wh + _g);                                   \
        }                                                                       \
        cp_commit();                                                            \
    } while (0)

    float acc[2][8][4];
    #pragma unroll
    for (int mt = 0; mt < 2; mt++)
        #pragma unroll
        for (int nt = 0; nt < 8; nt++)
            #pragma unroll
            for (int q = 0; q < 4; q++) acc[mt][nt][q] = 0.0f;

    LOADCHUNK(0, 0);
    LOADCHUNK(1, 1);
    LOADCHUNK(2, 2);

    for (int kc = 0; kc < 8; kc++) {
        if (kc < 6)      cp_wait2();   // chunks kc+1, kc+2 may still be in flight
        else if (kc == 6) cp_wait1();
        else              cp_wait0();
        __syncthreads();               // all warps done with chunk kc-1's buffer
        if (kc < 5) LOADCHUNK(kc + 3, (kc + 3) & 3);

        const uint32_t stg = sb + (kc & 3) * STAGE_SZ;
        #pragma unroll
        for (int ks = 0; ks < 4; ks++) {
            const uint32_t kb = ks * 32;  // 16 fp16 = 32 bytes per k-step
            uint32_t ah[2][4], bh[4][4];

            #pragma unroll
            for (int mt = 0; mt < 2; mt++)
                ldsm4(ah[mt], stg + aoff + mt * (16 * KPB) + kb + A_OFF);
            #pragma unroll
            for (int nt = 0; nt < 4; nt++)
                ldsm4(bh[nt], stg + boff + nt * (16 * KPB) + kb + B_OFF);

            // single pass: y * W  (16 distinct accumulators)
            #pragma unroll
            for (int nt = 0; nt < 4; nt++)
                #pragma unroll
                for (int mt = 0; mt < 2; mt++) {
                    mma16816(acc[mt][2 * nt],     ah[mt], bh[nt][0], bh[nt][1]);
                    mma16816(acc[mt][2 * nt + 1], ah[mt], bh[nt][2], bh[nt][3]);
                }
        }
    }

    // epilogue: c frag (m16n8): thread t -> rows {t/4, t/4+8}, cols {2(t%4), +1}
    {
        const int rgrp = lane >> 2;
        const int cgrp = 2 * (lane & 3);
        const float* b3e = b3 + e * H_;
        #pragma unroll
        for (int mt = 0; mt < 2; mt++) {
            const int r0 = wm * 32 + mt * 16 + rgrp;       // 0..127
            #pragma unroll
            for (int half = 0; half < 2; half++) {
                const int r = r0 + half * 8;
                const int bsel = (r < 64) ? b0 : b1;
                if (r >= 64 && !has_b1) continue;
                float* outr = out + ((size_t)bsel * 64 + (r & 63)) * 512;
                #pragma unroll
                for (int nt = 0; nt < 8; nt++) {
                    const int col = jq * 128 + wn * 64 + nt * 8 + cgrp;
                    float2 o;
                    o.x = acc[mt][nt][half * 2 + 0] + b3e[col];
                    o.y = acc[mt][nt][half * 2 + 1] + b3e[col + 1];
                    *(float2*)&outr[col] = o;
                }
            }
        }
    }
    #undef LOADCHUNK
}

// ---------------------------------------------------------------------------
extern "C" void kernel_launch(void* const* d_in, const int* in_sizes, int n_in,
                              void* d_out, int out_size)
{
    const float* actions = (const float*)d_in[0];
    const float* ts      = (const float*)d_in[1];
    const int*   cat     = (const int*)  d_in[2];
    const float* W1      = (const float*)d_in[3];
    const float* b1      = (const float*)d_in[4];
    const float* W2      = (const float*)d_in[5];
    const float* b2      = (const float*)d_in[6];
    const float* W3      = (const float*)d_in[7];
    const float* b3      = (const float*)d_in[8];
    float*       out     = (float*)d_out;

    const int smem_prep = (256 * 34 + 2 * 32 * 256) * 4;   // ~100 KB
    const int smem_y    = (32 * 256 + 64 * 32) * 4;        //  40 KB
    const int smem_mma  = 4 * STAGE_SZ;                    // 144 KB

    cudaFuncSetAttribute(k_prep, cudaFuncAttributeMaxDynamicSharedMemorySize, smem_prep);
    cudaFuncSetAttribute(k_y,    cudaFuncAttributeMaxDynamicSharedMemorySize, smem_y);
    cudaFuncSetAttribute(k_mma,  cudaFuncAttributeMaxDynamicSharedMemorySize, smem_mma);

    k_prep<<<769, 256, smem_prep>>>(ts, cat, W1, b1, W2, b2, W3);
    k_red <<<384, 512>>>();
    k_y   <<<dim3(B_, 2), 512, smem_y>>>(actions, cat);
    k_mma <<<dim3(272, 4), 256, smem_mma>>>(cat, b3, out);
}